// round 14
// baseline (speedup 1.0000x reference)
#include <cuda_runtime.h>
#include <cuda_fp16.h>
#include <math.h>

#define NTOK 4096
#define DM   1024
#define DFF  2048
#define NH   16
#define DK   64
#define NB   4
#define SEQ  1024
#define NE   8
#define PAIR_CAP 9216
#define NTILE72  72
#define WSZ  (1024*1024)   // words per DMxDM weight

// ---------------- fp32 scratch ----------------
__device__ float g_qd [NTOK*DM];
__device__ float g_kd [NTOK*DM];
__device__ float g_vd [NTOK*DM];
__device__ float g_dense_o[NTOK*DM];
__device__ float g_delta_o[NTOK*DM];
__device__ float g_x1 [NTOK*DM];
__device__ float g_xn1[NTOK*DM];
__device__ float g_xn2[NTOK*DM];
__device__ float g_ctx [NB*NH*DK*DK];
__device__ float g_ctxp[NB*NH*4*DK*DK];
__device__ float g_ksum[NB*NH*DK];
__device__ float g_ksump[NB*NH*4*DK];
__device__ float g_y2[(long long)PAIR_CAP*DM];
__device__ int   g_topk_idx[NTOK*2];
__device__ float g_topk_w [NTOK*2];
__device__ int   g_counts[NE];
__device__ int   g_cursor[NE];
__device__ int   g_off[NE+1];
__device__ int   g_tile_e[NTILE72];
__device__ int   g_tok[PAIR_CAP];
__device__ int   g_pair_pos[NTOK*2];

// ---------------- HL (interleaved hi/lo fp16) scratch, word units ----------------
__device__ unsigned g_xn1u[NTOK*DM];
__device__ unsigned g_qu  [NTOK*DM];
__device__ unsigned g_ku  [NTOK*DM];
__device__ unsigned g_vTu [DM*NTOK];
__device__ unsigned g_pu  [(long long)NB*NH*SEQ*SEQ];
__device__ unsigned g_actu[NTOK*DM];
__device__ unsigned g_dlu [NTOK*DM];
__device__ unsigned g_xn2u[NTOK*DM];
__device__ unsigned g_h1u [(long long)PAIR_CAP*DFF];
__device__ unsigned g_wu  [8LL*WSZ];
__device__ unsigned g_e1u [8LL*DM*DFF];
__device__ unsigned g_e2u [8LL*DFF*DM];

struct MD {
    const unsigned* a[6];
    float* f[6]; unsigned* h[6];
    int ldc[6]; int cT[6];
};

// ---------------- perm helpers ----------------
__device__ __forceinline__ int pperm(int p){ return ((p&3)<<1) | (p>>2); }
__device__ __forceinline__ int hlw(int p){ return 2*(p & ~7) + 2*pperm(p & 7); }

// ---------------- low-level ----------------
__device__ __forceinline__ void mma_f16(float* d,
        unsigned a0, unsigned a1, unsigned a2, unsigned a3,
        unsigned b0, unsigned b1){
    asm volatile("mma.sync.aligned.m16n8k16.row.col.f32.f16.f16.f32 "
        "{%0,%1,%2,%3}, {%4,%5,%6,%7}, {%8,%9}, {%0,%1,%2,%3};"
        : "+f"(d[0]),"+f"(d[1]),"+f"(d[2]),"+f"(d[3])
        : "r"(a0),"r"(a1),"r"(a2),"r"(a3),"r"(b0),"r"(b1));
}
__device__ __forceinline__ unsigned packh(__half x, __half y){
    return (unsigned)__half_as_ushort(x) | ((unsigned)__half_as_ushort(y) << 16);
}
__device__ __forceinline__ void split2(float x, float y, unsigned& hi, unsigned& lo){
    __half hx = __float2half_rn(x), hy = __float2half_rn(y);
    __half lx = __float2half_rn(x - __half2float(hx));
    __half ly = __float2half_rn(y - __half2float(hy));
    hi = packh(hx, hy);
    lo = packh(lx, ly);
}
__device__ __forceinline__ void cp16(unsigned saddr, const void* g, bool v){
    asm volatile("cp.async.ca.shared.global [%0], [%1], 16, %2;"
        :: "r"(saddr), "l"(g), "r"(v ? 16 : 0));
}
// FMA-pipe exp (no MUFU); exp(v)->0 for very negative v
__device__ __forceinline__ float fexp(float v){
    float y = v * 1.4426950408889634f;
    y = fmaxf(y, -126.0f);
    float n = floorf(y);
    float f = y - n;
    float p = 1.5403530e-4f;
    p = fmaf(p, f, 1.3333558e-3f);
    p = fmaf(p, f, 9.6181291e-3f);
    p = fmaf(p, f, 5.5504109e-2f);
    p = fmaf(p, f, 2.4022651e-1f);
    p = fmaf(p, f, 6.9314718e-1f);
    p = fmaf(p, f, 1.0f);
    return __int_as_float(((int)n + 127) << 23) * p;
}

__device__ __forceinline__ float warpSum(float v){
    #pragma unroll
    for (int o=16;o;o>>=1) v += __shfl_xor_sync(0xffffffffu, v, o);
    return v;
}
__device__ __forceinline__ float warpMax(float v){
    #pragma unroll
    for (int o=16;o;o>>=1) v = fmaxf(v, __shfl_xor_sync(0xffffffffu, v, o));
    return v;
}
__device__ __forceinline__ float blockSum(float v, float* red){
    v = warpSum(v);
    if ((threadIdx.x & 31) == 0) red[threadIdx.x>>5] = v;
    __syncthreads();
    if (threadIdx.x < 32) {
        float t = (threadIdx.x < 8) ? red[threadIdx.x] : 0.f;
        t = warpSum(t);
        if (threadIdx.x == 0) red[0] = t;
    }
    __syncthreads();
    float r = red[0];
    __syncthreads();
    return r;
}
__device__ __forceinline__ float blockMax(float v, float* red){
    v = warpMax(v);
    if ((threadIdx.x & 31) == 0) red[threadIdx.x>>5] = v;
    __syncthreads();
    if (threadIdx.x < 32) {
        float t = (threadIdx.x < 8) ? red[threadIdx.x] : -3.0e38f;
        t = warpMax(t);
        if (threadIdx.x == 0) red[0] = t;
    }
    __syncthreads();
    float r = red[0];
    __syncthreads();
    return r;
}

// ---------------- weight transpose + split -> HL (uint2 stores) ----------------
struct WP8 { const float* p[8]; };

__global__ void wsplit8_kernel(WP8 wp, unsigned* __restrict__ oB){
    __shared__ float ts[32][33];
    int mat = blockIdx.z;
    const float* W = wp.p[mat];
    unsigned* o = oB + (long long)mat*WSZ;
    int k0 = blockIdx.y*32, n0 = blockIdx.x*32;
    int tx = threadIdx.x, ty = threadIdx.y;   // 32 x 8
    #pragma unroll
    for (int i=0;i<4;i++)
        ts[ty+8*i][tx] = W[(long long)(k0+ty+8*i)*DM + n0 + tx];
    __syncthreads();
    int tid = ty*32 + tx;
    #pragma unroll
    for (int it=0; it<2; it++){
        int item = it*256 + tid;
        int n = item >> 4;
        int pr = item & 15;
        unsigned h,l; split2(ts[2*pr][n], ts[2*pr+1][n], h, l);
        *(uint2*)&o[(long long)(n0+n)*DM + hlw((k0>>1)+pr)] = make_uint2(h,l);
    }
}

__global__ void wsplit_kernel(const float* __restrict__ W,
                              unsigned* __restrict__ o, int K, int N){
    __shared__ float ts[32][33];
    W += (long long)blockIdx.z * K * N;
    o += (long long)blockIdx.z * K * N;
    int k0 = blockIdx.y*32, n0 = blockIdx.x*32;
    int tx = threadIdx.x, ty = threadIdx.y;
    #pragma unroll
    for (int i=0;i<4;i++)
        ts[ty+8*i][tx] = W[(long long)(k0+ty+8*i)*N + n0 + tx];
    __syncthreads();
    int tid = ty*32 + tx;
    #pragma unroll
    for (int it=0; it<2; it++){
        int item = it*256 + tid;
        int n = item >> 4;
        int pr = item & 15;
        unsigned h,l; split2(ts[2*pr][n], ts[2*pr+1][n], h, l);
        *(uint2*)&o[(long long)(n0+n)*K + hlw((k0>>1)+pr)] = make_uint2(h,l);
    }
}

// ---------------- layernorm (fp32 + HL out) ----------------
__global__ __launch_bounds__(256) void ln_kernel(const float* __restrict__ x,
                                                 const float* __restrict__ g,
                                                 const float* __restrict__ b,
                                                 float* __restrict__ y,
                                                 unsigned* __restrict__ yu){
    __shared__ float row[DM];
    __shared__ float red[8];
    long long base = (long long)blockIdx.x * DM;
    float s = 0.f;
    for (int i = threadIdx.x; i < DM; i += 256) { float v = x[base+i]; row[i] = v; s += v; }
    s = blockSum(s, red);
    float mu = s * (1.f/DM);
    float vs = 0.f;
    for (int i = threadIdx.x; i < DM; i += 256) { float d = row[i]-mu; vs += d*d; }
    vs = blockSum(vs, red);
    float rstd = rsqrtf(vs * (1.f/DM) + 1e-5f);
    unsigned* ob = yu + base;
    for (int i2 = threadIdx.x; i2 < DM/2; i2 += 256){
        int i = i2*2;
        float v0 = (row[i  ]-mu)*rstd*g[i  ] + b[i  ];
        float v1 = (row[i+1]-mu)*rstd*g[i+1] + b[i+1];
        if (y){ y[base+i] = v0; y[base+i+1] = v1; }
        unsigned h,l; split2(v0,v1,h,l);
        *(uint2*)&ob[hlw(i2)] = make_uint2(h,l);
    }
}

// ---------------- fused gate + combine + LN2 ----------------
__global__ __launch_bounds__(256) void combine_ln_kernel(
    const float* __restrict__ x, const float* __restrict__ dense,
    const float* __restrict__ delta, const float* __restrict__ xn1,
    const float* __restrict__ wg,
    const float* __restrict__ g, const float* __restrict__ b,
    float* __restrict__ x1, float* __restrict__ y, unsigned* __restrict__ yu)
{
    __shared__ float row[DM];
    __shared__ float red[8];
    long long base = (long long)blockIdx.x * DM;
    float p0=0.f, p1=0.f;
    for (int i = threadIdx.x; i < DM; i += 256){
        float xv = xn1[base+i];
        p0 += xv*wg[i*2+0];
        p1 += xv*wg[i*2+1];
    }
    p0 = blockSum(p0, red);
    p1 = blockSum(p1, red);
    float m = fmaxf(p0,p1);
    float e0 = expf(p0-m), e1 = expf(p1-m);
    float inv = 1.f/(e0+e1);
    float g0 = e0*inv, g1 = e1*inv;
    float s = 0.f;
    for (int i = threadIdx.x; i < DM; i += 256){
        float v = x[base+i] + g0*dense[base+i] + g1*delta[base+i];
        row[i] = v; x1[base+i] = v; s += v;
    }
    s = blockSum(s, red);
    float mu = s * (1.f/DM);
    float vs = 0.f;
    for (int i = threadIdx.x; i < DM; i += 256){ float d2 = row[i]-mu; vs += d2*d2; }
    vs = blockSum(vs, red);
    float rstd = rsqrtf(vs * (1.f/DM) + 1e-5f);
    unsigned* ob = yu + base;
    for (int i2 = threadIdx.x; i2 < DM/2; i2 += 256){
        int i = i2*2;
        float v0 = (row[i  ]-mu)*rstd*g[i  ] + b[i  ];
        float v1 = (row[i+1]-mu)*rstd*g[i+1] + b[i+1];
        y[base+i] = v0; y[base+i+1] = v1;
        unsigned h,l; split2(v0,v1,h,l);
        *(uint2*)&ob[hlw(i2)] = make_uint2(h,l);
    }
}

// ---------------- fp16x3 GEMM on HL operands ----------------
template<int NTILES>
__global__ __launch_bounds__(256,2) void gemm_hh_kernel(
    const unsigned* __restrict__ A, const unsigned* __restrict__ B,
    float* __restrict__ Cf, unsigned* __restrict__ Ch,
    int M, int N, int K, int ldaw, int ldbw, int ldc,
    int innerN,
    long long sAo, long long sAi, long long sBo, long long sBi,
    long long sCo, long long sCi,
    const int* __restrict__ rowIdx, const int* __restrict__ tileExpert,
    long long expSB, float alpha, int actMode, int cT,
    MD md, int nMulti,
    const int* __restrict__ moeOff, const int* __restrict__ moeCnt,
    const int* __restrict__ maskP)
{
    __shared__ unsigned As[3][128][16];
    __shared__ unsigned Bs[3][NTILES*16][16];

    int z  = blockIdx.z;
    int zo = z / innerN, zi = z - zo*innerN;
    if (nMulti > 0){
        A = md.a[zi];
        Cf = md.f[zi]; Ch = md.h[zi];
        ldc = md.ldc[zi]; cT = md.cT[zi];
    }
    const int tm0 = blockIdx.y * 128;
    const int tn0 = blockIdx.x * (NTILES*16);
    if (moeCnt){
        int e = tileExpert[blockIdx.y];
        if (tm0 >= moeOff[e] + moeCnt[e]) return;
    }
    A += zo*sAo + zi*sAi;
    long long boff = zo*sBo + zi*sBi;
    if (tileExpert) boff += (long long)tileExpert[blockIdx.y] * expSB;
    B += boff;
    long long coff = zo*sCo + zi*sCi;

    const int tid = threadIdx.x;
    const int lane = tid & 31;
    const int warp = tid >> 5;
    const int wm = (warp & 3) * 32;
    const int wn = (warp >> 2) * (NTILES*8);
    const int g = lane >> 2;
    const int q = lane & 3;

    // A loader: 2 threads/row, 8 words each
    const int lrow = tid >> 1;
    const int lsel = tid & 1;
    int grow = tm0 + lrow;
    bool aval = grow < M;
    int srcRow = aval ? (rowIdx ? (rowIdx[grow] & (NTOK-1)) : grow) : 0;
    const unsigned* Ap = A + (long long)srcRow * ldaw + lsel*8;
    unsigned aS = (unsigned)__cvta_generic_to_shared(&As[0][0][0])
                  + (unsigned)((lrow*16 + lsel*8)*4);

    // B loader
    const int tprB = 256/(NTILES*16);
    const int bwords = 16/tprB;
    const int browL = tid / tprB;
    const int bseg = tid % tprB;
    bool bval = (tn0 + browL) < N;
    int brow = bval ? (tn0 + browL) : 0;
    const unsigned* Bp = B + (long long)brow * ldbw + bseg*bwords;
    unsigned bS = (unsigned)__cvta_generic_to_shared(&Bs[0][0][0])
                  + (unsigned)((browL*16 + bseg*bwords)*4);
    const unsigned bStage = (unsigned)(NTILES*16*16*4);

    float acc[2][NTILES][4];
    #pragma unroll
    for (int mi=0;mi<2;mi++)
        #pragma unroll
        for (int ni=0;ni<NTILES;ni++)
            #pragma unroll
            for (int t=0;t<4;t++) acc[mi][ni][t]=0.f;

    const int nt = K >> 4;

    #define ISSUE_AT(T, ST) do{                                   \
        int _t = (T);                                              \
        if (_t < nt){                                              \
            unsigned _boA = (unsigned)((ST) * 8192);               \
            unsigned _boB = (unsigned)(ST) * bStage;               \
            int _kn = _t * 16;                                     \
            cp16(aS + _boA,      Ap + _kn,     aval);              \
            cp16(aS + _boA + 16, Ap + _kn + 4, aval);              \
            cp16(bS + _boB,      Bp + _kn,     bval);              \
            if (bwords == 8)                                       \
                cp16(bS + _boB + 16, Bp + _kn + 4, bval);          \
        }                                                          \
        asm volatile("cp.async.commit_group;");                    \
    }while(0)

    ISSUE_AT(0, 0);
    ISSUE_AT(1, 1);

    int buf = 0, fill = 2;
    for (int k = 0; k < nt; k++){
        asm volatile("cp.async.wait_group 1;");
        __syncthreads();
        ISSUE_AT(k+2, fill);
        {
            uint4 a1[2], a2[2];
            #pragma unroll
            for (int mi = 0; mi < 2; mi++){
                int row = wm + mi*16 + g;
                a1[mi] = *(const uint4*)&As[buf][row  ][4*q];
                a2[mi] = *(const uint4*)&As[buf][row+8][4*q];
            }
            #pragma unroll
            for (int ni = 0; ni < NTILES; ni++){
                int col = wn + ni*8 + g;
                uint4 bb = *(const uint4*)&Bs[buf][col][4*q];
                #pragma unroll
                for (int mi = 0; mi < 2; mi++){
                    mma_f16(acc[mi][ni], a1[mi].x, a2[mi].x, a1[mi].z, a2[mi].z, bb.x, bb.z);
                    mma_f16(acc[mi][ni], a1[mi].x, a2[mi].x, a1[mi].z, a2[mi].z, bb.y, bb.w);
                    mma_f16(acc[mi][ni], a1[mi].y, a2[mi].y, a1[mi].w, a2[mi].w, bb.x, bb.z);
                }
            }
        }
        buf  = (buf  == 2) ? 0 : buf  + 1;
        fill = (fill == 2) ? 0 : fill + 1;
    }
    #undef ISSUE_AT

    float* CfP = Cf ? (Cf + coff) : (float*)0;
    unsigned* ChP = Ch ? (Ch + coff) : (unsigned*)0;
    const int* mrow = maskP ? (maskP + ((long long)zo << 20)) : (const int*)0;
    #pragma unroll
    for (int mi = 0; mi < 2; mi++){
        #pragma unroll
        for (int rr = 0; rr < 2; rr++){
            int row = tm0 + wm + mi*16 + g + rr*8;
            if (row >= M) continue;
            #pragma unroll
            for (int ni = 0; ni < NTILES; ni++){
                int col = tn0 + wn + ni*8 + q*2;
                if (col >= N) continue;
                float v0 = acc[mi][ni][rr*2+0] * alpha;
                float v1 = acc[mi][ni][rr*2+1] * alpha;
                if (actMode == 1){
                    v0 = 0.5f * v0 * (1.f + erff(v0 * 0.70710678118654752f));
                    v1 = 0.5f * v1 * (1.f + erff(v1 * 0.70710678118654752f));
                }
                if (!cT){
                    if (CfP) *(float2*)&CfP[(long long)row*ldc + col] = make_float2(v0, v1);
                    if (ChP){
                        if (mrow){
                            int2 mm = *(const int2*)&mrow[(long long)row*1024 + col];
                            if (mm.x == 0) v0 = -60000.f;
                            if (mm.y == 0) v1 = -60000.f;
                        }
                        unsigned h,l; split2(v0,v1,h,l);
                        *(uint2*)&ChP[(long long)row*ldc + hlw(col>>1)] = make_uint2(h,l);
                    }
                } else {
                    int W = hlw(row >> 1);
                    int hs = row & 1;
                    {
                        __half h0 = __float2half_rn(v0);
                        unsigned* p = ChP + (long long)col*ldc;
                        ((__half*)(p + W    ))[hs] = h0;
                        ((__half*)(p + W + 1))[hs] = __float2half_rn(v0 - __half2float(h0));
                    }
                    if (col + 1 < N){
                        __half h1 = __float2half_rn(v1);
                        unsigned* p = ChP + (long long)(col+1)*ldc;
                        ((__half*)(p + W    ))[hs] = h1;
                        ((__half*)(p + W + 1))[hs] = __float2half_rn(v1 - __half2float(h1));
                    }
                }
            }
        }
    }
}

// ---------------- row softmax on pre-masked HL rows (in place, order-oblivious) ----------------
__global__ __launch_bounds__(256) void softmax_kernel(unsigned* __restrict__ P){
    long long r = blockIdx.x;
    unsigned* row32 = P + (r << 10);
    __shared__ float buf[SEQ];
    __shared__ float red[8];
    float mx = -3.0e38f;
    for (int j = threadIdx.x; j < SEQ/2; j += 256){
        uint2 u = *(uint2*)&row32[2*j];
        __half2 hv = *(__half2*)&u.x;
        __half2 lv = *(__half2*)&u.y;
        float v0 = __half2float(hv.x) + __half2float(lv.x);
        float v1 = __half2float(hv.y) + __half2float(lv.y);
        buf[2*j  ] = v0;
        buf[2*j+1] = v1;
        mx = fmaxf(mx, fmaxf(v0, v1));
    }
    mx = blockMax(mx, red);
    float sum = 0.f;
    for (int i = threadIdx.x; i < SEQ; i += 256){
        float e = fexp(buf[i]-mx);
        buf[i] = e; sum += e;
    }
    sum = blockSum(sum, red);
    float inv = 1.f / sum;
    for (int j = threadIdx.x; j < SEQ/2; j += 256){
        unsigned h,l; split2(buf[2*j]*inv, buf[2*j+1]*inv, h, l);
        *(uint2*)&row32[2*j] = make_uint2(h,l);
    }
}

// ---------------- delta branch (ksum folded into ctx1/ctx2) ----------------
__global__ __launch_bounds__(256) void ctx1_kernel(const float* __restrict__ kd,
                                                   const float* __restrict__ vd,
                                                   float* __restrict__ ctxp,
                                                   float* __restrict__ ksump){
    int z = blockIdx.x >> 2;
    int chunk = blockIdx.x & 3;
    int b = z >> 4, h = z & 15;
    const float* kbase = kd + ((long long)b*SEQ)*DM + h*DK;
    const float* vbase = vd + ((long long)b*SEQ)*DM + h*DK;
    __shared__ float ks[64][65];
    __shared__ float vs[64][65];
    int tid = threadIdx.x;
    int d0 = (tid >> 4) << 2;
    int e0 = (tid & 15) << 2;
    float acc[4][4];
    #pragma unroll
    for (int i=0;i<4;i++)
        #pragma unroll
        for (int j=0;j<4;j++) acc[i][j]=0.f;
    float ksacc = 0.f;

    for (int s0 = chunk*256; s0 < chunk*256+256; s0 += 64) {
        for (int t = tid; t < 64*16; t += 256) {
            int rr = t >> 4; int cc = (t & 15) << 2;
            float4 kv = *(const float4*)(kbase + (long long)(s0+rr)*DM + cc);
            float4 vv = *(const float4*)(vbase + (long long)(s0+rr)*DM + cc);
            ks[rr][cc+0]=kv.x; ks[rr][cc+1]=kv.y; ks[rr][cc+2]=kv.z; ks[rr][cc+3]=kv.w;
            vs[rr][cc+0]=vv.x; vs[rr][cc+1]=vv.y; vs[rr][cc+2]=vv.z; vs[rr][cc+3]=vv.w;
        }
        __syncthreads();
        if (tid < DK){
            #pragma unroll 8
            for (int rr=0; rr<64; rr++) ksacc += fmaxf(ks[rr][tid], 0.f);
        }
        #pragma unroll 4
        for (int ss=0; ss<64; ss++){
            float kr[4], vr[4];
            #pragma unroll
            for (int i=0;i<4;i++) kr[i]=ks[ss][d0+i];
            #pragma unroll
            for (int j=0;j<4;j++) vr[j]=vs[ss][e0+j];
            #pragma unroll
            for (int i=0;i<4;i++)
                #pragma unroll
                for (int j=0;j<4;j++) acc[i][j] += kr[i]*vr[j];
        }
        __syncthreads();
    }
    float* cbase = ctxp + ((long long)z*4 + chunk)*DK*DK;
    #pragma unroll
    for (int i=0;i<4;i++)
        #pragma unroll
        for (int j=0;j<4;j++)
            cbase[(d0+i)*DK + e0+j] = acc[i][j];
    if (tid < DK) ksump[((long long)z*4 + chunk)*DK + tid] = ksacc;
}

__global__ void ctx2_kernel(const float* __restrict__ ctxp, float* __restrict__ ctx,
                            const float* __restrict__ ksump, float* __restrict__ ksum){
    int z = blockIdx.x;
    const float* p = ctxp + (long long)z*4*DK*DK;
    float* o = ctx + (long long)z*DK*DK;
    for (int i = threadIdx.x; i < DK*DK; i += 256)
        o[i] = p[i] + p[DK*DK + i] + p[2*DK*DK + i] + p[3*DK*DK + i];
    if (threadIdx.x < DK){
        int d = threadIdx.x;
        float s = 0.f;
        #pragma unroll
        for (int c=0;c<4;c++) s += ksump[((long long)z*4 + c)*DK + d];
        ksum[z*DK + d] = s;
    }
}

__global__ __launch_bounds__(256) void delta_kernel(const float* __restrict__ qd,
                                                    const float* __restrict__ ctx,
                                                    const float* __restrict__ ksum,
                                                    unsigned* __restrict__ du){
    int z = blockIdx.x >> 2;
    int sc = blockIdx.x & 3;
    int b = z >> 4, h = z & 15;
    __shared__ float cs[DK*DK];
    __shared__ float kss[DK];
    for (int i = threadIdx.x; i < DK*DK; i += 256) cs[i] = ctx[(long long)z*DK*DK + i];
    if (threadIdx.x < DK) kss[threadIdx.x] = ksum[z*DK + threadIdx.x];
    __syncthreads();
    int s = sc*256 + threadIdx.x;
    const float* qrow = qd + ((long long)(b*SEQ + s))*DM + h*DK;
    float q[DK];
    #pragma unroll
    for (int d=0; d<DK; d+=4){
        float4 v = *(const float4*)(qrow + d);
        q[d+0]=fmaxf(v.x,0.f); q[d+1]=fmaxf(v.y,0.f);
        q[d+2]=fmaxf(v.z,0.f); q[d+3]=fmaxf(v.w,0.f);
    }
    float zv = 1e-6f;
    #pragma unroll
    for (int d=0; d<DK; d++) zv += q[d]*kss[d];
    float invz = 1.f / zv;
    unsigned* ob = du + ((long long)(b*SEQ + s))*DM + h*DK;
    for (int e=0; e<DK; e+=2){
        float a0 = 0.f, a1 = 0.f;
        #pragma unroll
        for (int d=0; d<DK; d++){
            a0 += q[d]*cs[d*DK + e];
            a1 += q[d]*cs[d*DK + e+1];
        }
        unsigned hh,ll; split2(a0*invz, a1*invz, hh, ll);
        *(uint2*)&ob[hlw(e>>1)] = make_uint2(hh,ll);
    }
}

// ---------------- router / moe plumbing / final ----------------
__global__ __launch_bounds__(256) void router_kernel(const float* __restrict__ xn2,
                                                     const float* __restrict__ wr,
                                                     int* __restrict__ topk_idx,
                                                     float* __restrict__ topk_w,
                                                     int* __restrict__ counts){
    int t = blockIdx.x;
    float p[NE];
    #pragma unroll
    for (int e=0;e<NE;e++) p[e]=0.f;
    for (int k = threadIdx.x; k < DM; k += 256){
        float xv = xn2[(long long)t*DM + k];
        #pragma unroll
        for (int e=0;e<NE;e++) p[e] += xv*wr[k*NE + e];
    }
    __shared__ float part[NE][8];
    int w = threadIdx.x >> 5;
    #pragma unroll
    for (int e=0;e<NE;e++){
        float v = warpSum(p[e]);
        if ((threadIdx.x & 31)==0) part[e][w] = v;
    }
    __syncthreads();
    if (threadIdx.x == 0){
        float lg[NE];
        for (int e=0;e<NE;e++){
            float s=0.f;
            for (int ww=0; ww<8; ww++) s += part[e][ww];
            lg[e]=s;
        }
        int i0=0; float v0=lg[0];
        for (int e=1;e<NE;e++) if (lg[e]>v0){v0=lg[e];i0=e;}
        int i1=-1; float v1=-3.0e38f;
        for (int e=0;e<NE;e++) if (e!=i0 && lg[e]>v1){v1=lg[e];i1=e;}
        float e1 = expf(v1-v0);
        float inv = 1.f/(1.f+e1);
        topk_idx[t*2+0]=i0; topk_idx[t*2+1]=i1;
        topk_w[t*2+0]=inv;  topk_w[t*2+1]=e1*inv;
        atomicAdd(&counts[i0],1); atomicAdd(&counts[i1],1);
    }
}

__global__ void prep_kernel(int* counts, int* cursor, int* tok){
    int i = blockIdx.x*256 + threadIdx.x;
    if (i < NE){ counts[i]=0; cursor[i]=0; }
    if (i < PAIR_CAP) tok[i]=0;
}

__global__ void scan_kernel(const int* counts, int* off, int* tile_e){
    if (threadIdx.x==0 && blockIdx.x==0){
        int o = 0;
        off[0]=0;
        for (int e=0;e<NE;e++){ o += (counts[e]+127)&~127; off[e+1]=o; }
        for (int t=0;t<NTILE72;t++){
            int row = t*128;
            int ee = NE-1;
            for (int i=0;i<NE;i++){ if (row < off[i+1]) { ee=i; break; } }
            tile_e[t]=ee;
        }
    }
}

__global__ void place_kernel(const int* __restrict__ topk_idx,
                             const int* __restrict__ off,
                             int* cursor, int* tok, int* pair_pos){
    int t = blockIdx.x*256 + threadIdx.x;
    if (t >= NTOK) return;
    for (int k=0;k<2;k++){
        int e = topk_idx[t*2+k];
        int pos = atomicAdd(&cursor[e],1);
        int r = off[e] + pos;
        tok[r] = t;
        pair_pos[t*2+k] = r;
    }
}

__global__ void final_kernel(const float* __restrict__ x1,
                             const float* __restrict__ y2,
                             const float* __restrict__ topk_w,
                             const int* __restrict__ pair_pos,
                             float* __restrict__ out){
    long long i = ((long long)blockIdx.x*256 + threadIdx.x) * 4;
    int t = (int)(i >> 10);
    int c = (int)(i & 1023);
    float w0 = topk_w[t*2+0], w1 = topk_w[t*2+1];
    long long b0 = (long long)pair_pos[t*2+0]*DM + c;
    long long b1 = (long long)pair_pos[t*2+1]*DM + c;
    float4 a  = *(const float4*)&x1[i];
    float4 y0 = *(const float4*)&y2[b0];
    float4 y1 = *(const float4*)&y2[b1];
    float4 r;
    r.x = a.x + w0*y0.x + w1*y1.x;
    r.y = a.y + w0*y0.y + w1*y1.y;
    r.z = a.z + w0*y0.z + w1*y1.z;
    r.w = a.w + w0*y0.w + w1*y1.w;
    *(float4*)&out[i] = r;
}

// ---------------- host side ----------------
static void gemm(const unsigned* A, const unsigned* B,
                 float* Cf, unsigned* Ch,
                 int M, int N, int K, int ldaw, int ldbw, int ldc,
                 int batch, int innerN,
                 long long sAo, long long sAi, long long sBo, long long sBi,
                 long long sCo, long long sCi,
                 const int* rowIdx, const int* tileE, long long expSB,
                 float alpha, int act, int cT,
                 int tile64, const MD& md, int nMulti,
                 const int* moeOff, const int* moeCnt, const int* maskP){
    if (tile64){
        dim3 grid((N+63)/64, (M+127)/128, batch);
        gemm_hh_kernel<4><<<grid, 256>>>(A,B,Cf,Ch,M,N,K,ldaw,ldbw,ldc,innerN,
                                         sAo,sAi,sBo,sBi,sCo,sCi,
                                         rowIdx,tileE,expSB,alpha,act,cT,md,nMulti,
                                         moeOff,moeCnt,maskP);
    } else {
        dim3 grid((N+127)/128, (M+127)/128, batch);
        gemm_hh_kernel<8><<<grid, 256>>>(A,B,Cf,Ch,M,N,K,ldaw,ldbw,ldc,innerN,
                                         sAo,sAi,sBo,sBi,sCo,sCi,
                                         rowIdx,tileE,expSB,alpha,act,cT,md,nMulti,
                                         moeOff,moeCnt,maskP);
    }
}

extern "C" void kernel_launch(void* const* d_in, const int* in_sizes, int n_in,
                              void* d_out, int out_size){
    const float* x        = (const float*)d_in[0];
    const int*   mask     = (const int*)  d_in[1];
    const float* ln1_g    = (const float*)d_in[2];
    const float* ln1_b    = (const float*)d_in[3];
    const float* wq       = (const float*)d_in[4];
    const float* wk       = (const float*)d_in[5];
    const float* wv       = (const float*)d_in[6];
    const float* wo       = (const float*)d_in[7];
    const float* wqd      = (const float*)d_in[8];
    const float* wkd      = (const float*)d_in[9];
    const float* wvd      = (const float*)d_in[10];
    const float* wod      = (const float*)d_in[11];
    const float* w_gate   = (const float*)d_in[12];
    const float* ln2_g    = (const float*)d_in[13];
    const float* ln2_b    = (const float*)d_in[14];
    const float* w_router = (const float*)d_in[15];
    const float* e_w1     = (const float*)d_in[16];
    const float* e_w2     = (const float*)d_in[17];
    float* out = (float*)d_out;

    float *xn1,*qd,*kd,*vd,*dense_o,*delta_o,*x1,*xn2,*ctx,*ctxp,*ksum,*ksump,*y2,*topk_w;
    int *topk_idx,*counts,*cursor,*off,*tile_e,*tok,*pair_pos;
    unsigned *xn1u,*qu,*ku,*vTu,*pu,*actu,*dlu,*xn2u,*h1u,*wu,*e1u,*e2u;

    cudaGetSymbolAddress((void**)&xn1,     g_xn1);
    cudaGetSymbolAddress((void**)&qd,      g_qd);
    cudaGetSymbolAddress((void**)&kd,      g_kd);
    cudaGetSymbolAddress((void**)&vd,      g_vd);
    cudaGetSymbolAddress((void**)&dense_o, g_dense_o);
    cudaGetSymbolAddress((void**)&delta_o, g_delta_o);
    cudaGetSymbolAddress((void**)&x1,      g_x1);
    cudaGetSymbolAddress((void**)&xn2,     g_xn2);
    cudaGetSymbolAddress((void**)&ctx,     g_ctx);
    cudaGetSymbolAddress((void**)&ctxp,    g_ctxp);
    cudaGetSymbolAddress((void**)&ksum,    g_ksum);
    cudaGetSymbolAddress((void**)&ksump,   g_ksump);
    cudaGetSymbolAddress((void**)&y2,      g_y2);
    cudaGetSymbolAddress((void**)&topk_w,  g_topk_w);
    cudaGetSymbolAddress((void**)&topk_idx,g_topk_idx);
    cudaGetSymbolAddress((void**)&counts,  g_counts);
    cudaGetSymbolAddress((void**)&cursor,  g_cursor);
    cudaGetSymbolAddress((void**)&off,     g_off);
    cudaGetSymbolAddress((void**)&tile_e,  g_tile_e);
    cudaGetSymbolAddress((void**)&tok,     g_tok);
    cudaGetSymbolAddress((void**)&pair_pos,g_pair_pos);
    cudaGetSymbolAddress((void**)&xn1u,    g_xn1u);
    cudaGetSymbolAddress((void**)&qu,      g_qu);
    cudaGetSymbolAddress((void**)&ku,      g_ku);
    cudaGetSymbolAddress((void**)&vTu,     g_vTu);
    cudaGetSymbolAddress((void**)&pu,      g_pu);
    cudaGetSymbolAddress((void**)&actu,    g_actu);
    cudaGetSymbolAddress((void**)&dlu,     g_dlu);
    cudaGetSymbolAddress((void**)&xn2u,    g_xn2u);
    cudaGetSymbolAddress((void**)&h1u,     g_h1u);
    cudaGetSymbolAddress((void**)&wu,      g_wu);
    cudaGetSymbolAddress((void**)&e1u,     g_e1u);
    cudaGetSymbolAddress((void**)&e2u,     g_e2u);

    const long long TOKD = (long long)SEQ*DM;
    MD md0; memset(&md0, 0, sizeof(md0));

    // 0: LN1
    ln_kernel<<<NTOK,256>>>(x, ln1_g, ln1_b, xn1, xn1u);
    // 1: dense weight splits
    WP8 wp;
    wp.p[0]=wq; wp.p[1]=wk; wp.p[2]=wv; wp.p[3]=wqd;
    wp.p[4]=wkd; wp.p[5]=wvd; wp.p[6]=wo; wp.p[7]=wod;
    wsplit8_kernel<<<dim3(32,32,8), dim3(32,8)>>>(wp, wu);

    // 2: all 6 projections (batched)
    {
        MD md; memset(&md, 0, sizeof(md));
        for (int z=0; z<6; z++){ md.a[z]=xn1u; md.ldc[z]=DM; md.cT[z]=0; }
        md.h[0]=qu;
        md.h[1]=ku;
        md.h[2]=vTu; md.ldc[2]=NTOK; md.cT[2]=1;
        md.f[3]=qd;
        md.f[4]=kd;
        md.f[5]=vd;
        gemm(xn1u, wu, 0,0,
             NTOK,DM,DM, DM,DM,DM, 6,6,
             0,0, 0,WSZ, 0,0,
             0,0,0, 1.f,0,0, 0, md, 6, 0,0, 0);
    }

    // 3: scores = Q @ K^T / 8, mask applied in epilogue -> HL   <-- ncu target
    gemm(qu, ku, 0,pu, SEQ,SEQ,DK, DM,DM,SEQ,
         NB*NH, NH,
         TOKD, DK,  TOKD, DK,  (long long)NH*SEQ*SEQ, (long long)SEQ*SEQ,
         0,0,0, 0.125f,0,0, 0, md0, 0, 0,0, mask);

    // 4: softmax in place (no mask read)
    softmax_kernel<<<NB*NH*SEQ, 256>>>(pu);

    // 5: attnctx = P @ V (64-wide tile) -> HL natural
    gemm(pu, vTu, 0,actu, SEQ,DK,SEQ, SEQ,NTOK,DM,
         NB*NH, NH,
         (long long)NH*SEQ*SEQ, (long long)SEQ*SEQ,  SEQ, (long long)DK*NTOK,
         TOKD, DK,
         0,0,0, 1.f,0,0, 1, md0, 0, 0,0, 0);

    // delta branch (ksum fused)
    ctx1_kernel<<<NB*NH*4, 256>>>(kd, vd, ctxp, ksump);
    ctx2_kernel<<<NB*NH, 256>>>(ctxp, ctx, ksump, ksum);
    delta_kernel<<<NB*NH*4, 256>>>(qd, ctx, ksum, dlu);

    // output projections, batched 2
    {
        MD md; memset(&md, 0, sizeof(md));
        md.a[0]=actu; md.f[0]=dense_o; md.ldc[0]=DM; md.cT[0]=0;
        md.a[1]=dlu;  md.f[1]=delta_o; md.ldc[1]=DM; md.cT[1]=0;
        gemm(actu, wu+6LL*WSZ, 0,0,
             NTOK,DM,DM, DM,DM,DM, 2,2,
             0,0, 0,WSZ, 0,0,
             0,0,0, 1.f,0,0, 0, md, 2, 0,0, 0);
    }

    // fused gate + combine + LN2
    combine_ln_kernel<<<NTOK,256>>>(x, dense_o, delta_o, xn1, w_gate,
                                    ln2_g, ln2_b, x1, xn2, xn2u);

    // routing
    prep_kernel<<<(PAIR_CAP+255)/256, 256>>>(counts, cursor, tok);
    router_kernel<<<NTOK, 256>>>(xn2, w_router, topk_idx, topk_w, counts);
    scan_kernel<<<1,32>>>(counts, off, tile_e);
    place_kernel<<<(NTOK+255)/256, 256>>>(topk_idx, off, cursor, tok, pair_pos);

    // expert weight splits (moved late; only needed by MoE GEMMs)
    wsplit_kernel<<<dim3(DFF/32, DM/32, NE), dim3(32,8)>>>(e_w1, e1u, DM, DFF);

    // expert GEMM1 (gathered, gelu) -> h1 HL ; pad tiles skipped
    gemm(xn2u, e1u, 0,h1u, PAIR_CAP,DFF,DM, DM,DM,DFF,
         1,1, 0,0,0,0,0,0,
         tok, tile_e, (long long)DM*DFF, 1.f,1,0, 0, md0, 0, off, counts, 0);

    wsplit_kernel<<<dim3(DM/32, DFF/32, NE), dim3(32,8)>>>(e_w2, e2u, DFF, DM);

    // expert GEMM2 -> y2 fp32 ; pad tiles skipped
    gemm(h1u, e2u, y2,0, PAIR_CAP,DM,DFF, DFF,DFF,DM,
         1,1, 0,0,0,0,0,0,
         0, tile_e, (long long)DFF*DM, 1.f,0,0, 0, md0, 0, off, counts, 0);

    // final combine (float4)
    final_kernel<<<NTOK*DM/1024, 256>>>(x1, y2, topk_w, pair_pos, out);
}

// round 15
// speedup vs baseline: 1.1104x; 1.1104x over previous
#include <cuda_runtime.h>
#include <cuda_fp16.h>
#include <math.h>

#define NTOK 4096
#define DM   1024
#define DFF  2048
#define NH   16
#define DK   64
#define NB   4
#define SEQ  1024
#define NE   8
#define PAIR_CAP 9216
#define NTILE72  72
#define WSZ  (1024*1024)

// ---------------- fp32 scratch ----------------
__device__ float g_qd [NTOK*DM];
__device__ float g_kd [NTOK*DM];
__device__ float g_vd [NTOK*DM];
__device__ float g_dense_o[NTOK*DM];
__device__ float g_delta_o[NTOK*DM];
__device__ float g_x1 [NTOK*DM];
__device__ float g_xn1[NTOK*DM];
__device__ float g_xn2[NTOK*DM];
__device__ float g_ctx [NB*NH*DK*DK];
__device__ float g_ctxp[NB*NH*4*DK*DK];
__device__ float g_ksum[NB*NH*DK];
__device__ float g_ksump[NB*NH*4*DK];
__device__ float g_y2[(long long)PAIR_CAP*DM];
__device__ int   g_topk_idx[NTOK*2];
__device__ float g_topk_w [NTOK*2];
__device__ int   g_counts[NE];
__device__ int   g_cursor[NE];
__device__ int   g_off[NE+1];
__device__ int   g_tile_e[NTILE72];
__device__ int   g_tok[PAIR_CAP];
__device__ int   g_pair_pos[NTOK*2];
__device__ unsigned g_mb[NB*SEQ*32];     // packed mask bits

// ---------------- HL scratch ----------------
__device__ unsigned g_xn1u[NTOK*DM];
__device__ unsigned g_qu  [NTOK*DM];
__device__ unsigned g_ku  [NTOK*DM];
__device__ unsigned g_vTu [DM*NTOK];
__device__ unsigned g_actu[NTOK*DM];
__device__ unsigned g_dlu [NTOK*DM];
__device__ unsigned g_xn2u[NTOK*DM];
__device__ unsigned g_h1u [(long long)PAIR_CAP*DFF];
__device__ unsigned g_wu  [8LL*WSZ];
__device__ unsigned g_e1u [8LL*DM*DFF];
__device__ unsigned g_e2u [8LL*DFF*DM];

struct MD {
    const unsigned* a[6];
    float* f[6]; unsigned* h[6];
    int ldc[6]; int cT[6];
};

// ---------------- perm helpers ----------------
__device__ __forceinline__ int pperm(int p){ return ((p&3)<<1) | (p>>2); }
__device__ __forceinline__ int hlw(int p){ return 2*(p & ~7) + 2*pperm(p & 7); }

// ---------------- low-level ----------------
__device__ __forceinline__ void mma_f16(float* d,
        unsigned a0, unsigned a1, unsigned a2, unsigned a3,
        unsigned b0, unsigned b1){
    asm volatile("mma.sync.aligned.m16n8k16.row.col.f32.f16.f16.f32 "
        "{%0,%1,%2,%3}, {%4,%5,%6,%7}, {%8,%9}, {%0,%1,%2,%3};"
        : "+f"(d[0]),"+f"(d[1]),"+f"(d[2]),"+f"(d[3])
        : "r"(a0),"r"(a1),"r"(a2),"r"(a3),"r"(b0),"r"(b1));
}
__device__ __forceinline__ unsigned packh(__half x, __half y){
    return (unsigned)__half_as_ushort(x) | ((unsigned)__half_as_ushort(y) << 16);
}
__device__ __forceinline__ void split2(float x, float y, unsigned& hi, unsigned& lo){
    __half hx = __float2half_rn(x), hy = __float2half_rn(y);
    __half lx = __float2half_rn(x - __half2float(hx));
    __half ly = __float2half_rn(y - __half2float(hy));
    hi = packh(hx, hy);
    lo = packh(lx, ly);
}
__device__ __forceinline__ void cp16(unsigned saddr, const void* g, bool v){
    asm volatile("cp.async.ca.shared.global [%0], [%1], 16, %2;"
        :: "r"(saddr), "l"(g), "r"(v ? 16 : 0));
}
__device__ __forceinline__ float fexp(float v){
    float y = v * 1.4426950408889634f;
    y = fmaxf(y, -126.0f);
    float n = floorf(y);
    float f = y - n;
    float p = 1.5403530e-4f;
    p = fmaf(p, f, 1.3333558e-3f);
    p = fmaf(p, f, 9.6181291e-3f);
    p = fmaf(p, f, 5.5504109e-2f);
    p = fmaf(p, f, 2.4022651e-1f);
    p = fmaf(p, f, 6.9314718e-1f);
    p = fmaf(p, f, 1.0f);
    return __int_as_float(((int)n + 127) << 23) * p;
}

__device__ __forceinline__ float warpSum(float v){
    #pragma unroll
    for (int o=16;o;o>>=1) v += __shfl_xor_sync(0xffffffffu, v, o);
    return v;
}
__device__ __forceinline__ float blockSum(float v, float* red){
    v = warpSum(v);
    if ((threadIdx.x & 31) == 0) red[threadIdx.x>>5] = v;
    __syncthreads();
    if (threadIdx.x < 32) {
        float t = (threadIdx.x < 8) ? red[threadIdx.x] : 0.f;
        t = warpSum(t);
        if (threadIdx.x == 0) red[0] = t;
    }
    __syncthreads();
    float r = red[0];
    __syncthreads();
    return r;
}

// ---------------- mask bit packing ----------------
__global__ void maskpack_kernel(const int* __restrict__ mask, unsigned* __restrict__ mb){
    int idx = blockIdx.x*8 + (threadIdx.x>>5);
    int lane = threadIdx.x & 31;
    int r = idx >> 5, w = idx & 31;
    int v = mask[(long long)r*1024 + w*32 + lane];
    unsigned bits = __ballot_sync(0xffffffffu, v != 0);
    if (lane == 0) mb[r*32 + w] = bits;
}

// ---------------- weight transpose + split -> HL ----------------
struct WP8 { const float* p[8]; };

__global__ void wsplit8_kernel(WP8 wp, unsigned* __restrict__ oB){
    __shared__ float ts[32][33];
    int mat = blockIdx.z;
    const float* W = wp.p[mat];
    unsigned* o = oB + (long long)mat*WSZ;
    int k0 = blockIdx.y*32, n0 = blockIdx.x*32;
    int tx = threadIdx.x, ty = threadIdx.y;
    #pragma unroll
    for (int i=0;i<4;i++)
        ts[ty+8*i][tx] = W[(long long)(k0+ty+8*i)*DM + n0 + tx];
    __syncthreads();
    int tid = ty*32 + tx;
    #pragma unroll
    for (int it=0; it<2; it++){
        int item = it*256 + tid;
        int n = item >> 4;
        int pr = item & 15;
        unsigned h,l; split2(ts[2*pr][n], ts[2*pr+1][n], h, l);
        *(uint2*)&o[(long long)(n0+n)*DM + hlw((k0>>1)+pr)] = make_uint2(h,l);
    }
}

__global__ void wsplit_kernel(const float* __restrict__ W,
                              unsigned* __restrict__ o, int K, int N){
    __shared__ float ts[32][33];
    W += (long long)blockIdx.z * K * N;
    o += (long long)blockIdx.z * K * N;
    int k0 = blockIdx.y*32, n0 = blockIdx.x*32;
    int tx = threadIdx.x, ty = threadIdx.y;
    #pragma unroll
    for (int i=0;i<4;i++)
        ts[ty+8*i][tx] = W[(long long)(k0+ty+8*i)*N + n0 + tx];
    __syncthreads();
    int tid = ty*32 + tx;
    #pragma unroll
    for (int it=0; it<2; it++){
        int item = it*256 + tid;
        int n = item >> 4;
        int pr = item & 15;
        unsigned h,l; split2(ts[2*pr][n], ts[2*pr+1][n], h, l);
        *(uint2*)&o[(long long)(n0+n)*K + hlw((k0>>1)+pr)] = make_uint2(h,l);
    }
}

// ---------------- layernorm ----------------
__global__ __launch_bounds__(256) void ln_kernel(const float* __restrict__ x,
                                                 const float* __restrict__ g,
                                                 const float* __restrict__ b,
                                                 float* __restrict__ y,
                                                 unsigned* __restrict__ yu){
    __shared__ float row[DM];
    __shared__ float red[8];
    long long base = (long long)blockIdx.x * DM;
    float s = 0.f;
    for (int i = threadIdx.x; i < DM; i += 256) { float v = x[base+i]; row[i] = v; s += v; }
    s = blockSum(s, red);
    float mu = s * (1.f/DM);
    float vs = 0.f;
    for (int i = threadIdx.x; i < DM; i += 256) { float d = row[i]-mu; vs += d*d; }
    vs = blockSum(vs, red);
    float rstd = rsqrtf(vs * (1.f/DM) + 1e-5f);
    unsigned* ob = yu + base;
    for (int i2 = threadIdx.x; i2 < DM/2; i2 += 256){
        int i = i2*2;
        float v0 = (row[i  ]-mu)*rstd*g[i  ] + b[i  ];
        float v1 = (row[i+1]-mu)*rstd*g[i+1] + b[i+1];
        if (y){ y[base+i] = v0; y[base+i+1] = v1; }
        unsigned h,l; split2(v0,v1,h,l);
        *(uint2*)&ob[hlw(i2)] = make_uint2(h,l);
    }
}

// ---------------- fused gate + combine + LN2 ----------------
__global__ __launch_bounds__(256) void combine_ln_kernel(
    const float* __restrict__ x, const float* __restrict__ dense,
    const float* __restrict__ delta, const float* __restrict__ xn1,
    const float* __restrict__ wg,
    const float* __restrict__ g, const float* __restrict__ b,
    float* __restrict__ x1, float* __restrict__ y, unsigned* __restrict__ yu)
{
    __shared__ float row[DM];
    __shared__ float red[8];
    long long base = (long long)blockIdx.x * DM;
    float p0=0.f, p1=0.f;
    for (int i = threadIdx.x; i < DM; i += 256){
        float xv = xn1[base+i];
        p0 += xv*wg[i*2+0];
        p1 += xv*wg[i*2+1];
    }
    p0 = blockSum(p0, red);
    p1 = blockSum(p1, red);
    float m = fmaxf(p0,p1);
    float e0 = expf(p0-m), e1 = expf(p1-m);
    float inv = 1.f/(e0+e1);
    float g0 = e0*inv, g1 = e1*inv;
    float s = 0.f;
    for (int i = threadIdx.x; i < DM; i += 256){
        float v = x[base+i] + g0*dense[base+i] + g1*delta[base+i];
        row[i] = v; x1[base+i] = v; s += v;
    }
    s = blockSum(s, red);
    float mu = s * (1.f/DM);
    float vs = 0.f;
    for (int i = threadIdx.x; i < DM; i += 256){ float d2 = row[i]-mu; vs += d2*d2; }
    vs = blockSum(vs, red);
    float rstd = rsqrtf(vs * (1.f/DM) + 1e-5f);
    unsigned* ob = yu + base;
    for (int i2 = threadIdx.x; i2 < DM/2; i2 += 256){
        int i = i2*2;
        float v0 = (row[i  ]-mu)*rstd*g[i  ] + b[i  ];
        float v1 = (row[i+1]-mu)*rstd*g[i+1] + b[i+1];
        y[base+i] = v0; y[base+i+1] = v1;
        unsigned h,l; split2(v0,v1,h,l);
        *(uint2*)&ob[hlw(i2)] = make_uint2(h,l);
    }
}

// ---------------- fused flash attention (scores + softmax + PV) ----------------
// grid (SEQ/128, NB*NH), 256 threads. All operands HL fp16x3.
__global__ __launch_bounds__(256,2) void fattn_kernel(
    const unsigned* __restrict__ Q, const unsigned* __restrict__ Kt,
    const unsigned* __restrict__ Vt, const unsigned* __restrict__ mb,
    unsigned* __restrict__ O)
{
    __shared__ unsigned skv[8192];    // 32KB: K tile [0..4095], V tile [4096..8191]
    const int bh = blockIdx.y;
    const int b = bh >> 4, h = bh & 15;
    const int tm0 = blockIdx.x * 128;
    const int tid = threadIdx.x;
    const int lane = tid & 31;
    const int warp = tid >> 5;
    const int g = lane >> 2;
    const int q = lane & 3;
    const long long tokB = (long long)b * SEQ;

    unsigned sb = (unsigned)__cvta_generic_to_shared(&skv[0]);

    // ---- stage Q tile (128x64 words) and read per-warp fragments ----
    #pragma unroll
    for (int j = 0; j < 8; j++){
        int w = tid*4 + j*1024;
        int row = w >> 6, col = w & 63;
        cp16(sb + w*4, Q + (tokB + tm0 + row)*DM + h*64 + col, true);
    }
    asm volatile("cp.async.commit_group;");
    asm volatile("cp.async.wait_group 0;");
    __syncthreads();
    uint4 qa[4][2];
    {
        int r0 = warp*16 + g;
        #pragma unroll
        for (int kk = 0; kk < 4; kk++){
            qa[kk][0] = *(const uint4*)&skv[r0*64      + kk*16 + 4*q];
            qa[kk][1] = *(const uint4*)&skv[(r0+8)*64  + kk*16 + 4*q];
        }
    }
    __syncthreads();

    float m0 = -3.0e38f, m1 = -3.0e38f, l0 = 0.f, l1 = 0.f;
    float Oa[8][4];
    #pragma unroll
    for (int ni=0;ni<8;ni++)
        #pragma unroll
        for (int t=0;t<4;t++) Oa[ni][t] = 0.f;

    const int qrow_g  = tm0 + warp*16 + g;
    const int qrow_g8 = qrow_g + 8;
    const unsigned* mbg  = mb + ((long long)(b*SEQ + qrow_g ))*32;
    const unsigned* mbg8 = mb + ((long long)(b*SEQ + qrow_g8))*32;

    for (int kt = 0; kt < 16; kt++){
        // ---- load K, V tiles (single buffered) ----
        #pragma unroll
        for (int j = 0; j < 4; j++){
            int w = tid*4 + j*1024;
            int row = w >> 6, col = w & 63;
            cp16(sb + w*4,          Kt + (tokB + kt*64 + row)*DM + h*64 + col, true);
            cp16(sb + 16384 + w*4,  Vt + (long long)(h*64 + row)*NTOK + tokB + kt*64 + col, true);
        }
        asm volatile("cp.async.commit_group;");
        asm volatile("cp.async.wait_group 0;");
        __syncthreads();

        // ---- S = Q @ K^T (fp16x3) ----
        float S_[8][4];
        #pragma unroll
        for (int ni=0;ni<8;ni++)
            #pragma unroll
            for (int t=0;t<4;t++) S_[ni][t] = 0.f;
        #pragma unroll
        for (int kk = 0; kk < 4; kk++){
            #pragma unroll
            for (int ni = 0; ni < 8; ni++){
                uint4 bb = *(const uint4*)&skv[(ni*8+g)*64 + kk*16 + 4*q];
                mma_f16(S_[ni], qa[kk][0].x, qa[kk][1].x, qa[kk][0].z, qa[kk][1].z, bb.x, bb.z);
                mma_f16(S_[ni], qa[kk][0].x, qa[kk][1].x, qa[kk][0].z, qa[kk][1].z, bb.y, bb.w);
                mma_f16(S_[ni], qa[kk][0].y, qa[kk][1].y, qa[kk][0].w, qa[kk][1].w, bb.x, bb.z);
            }
        }

        // ---- scale + mask ----
        uint2 mg  = *(const uint2*)&mbg [kt*2];
        uint2 mg8 = *(const uint2*)&mbg8[kt*2];
        #pragma unroll
        for (int ni = 0; ni < 8; ni++){
            int c = ni*8 + 2*q;
            unsigned wg_  = (c < 32) ? mg.x  : mg.y;
            unsigned wg8_ = (c < 32) ? mg8.x : mg8.y;
            int bitp = c & 31;
            S_[ni][0] = ((wg_ >> bitp) & 1)      ? S_[ni][0]*0.125f : -1e9f;
            S_[ni][1] = ((wg_ >> (bitp+1)) & 1)  ? S_[ni][1]*0.125f : -1e9f;
            S_[ni][2] = ((wg8_ >> bitp) & 1)     ? S_[ni][2]*0.125f : -1e9f;
            S_[ni][3] = ((wg8_ >> (bitp+1)) & 1) ? S_[ni][3]*0.125f : -1e9f;
        }

        // ---- online softmax ----
        float rm0 = -3.0e38f, rm1 = -3.0e38f;
        #pragma unroll
        for (int ni = 0; ni < 8; ni++){
            rm0 = fmaxf(rm0, fmaxf(S_[ni][0], S_[ni][1]));
            rm1 = fmaxf(rm1, fmaxf(S_[ni][2], S_[ni][3]));
        }
        rm0 = fmaxf(rm0, __shfl_xor_sync(0xffffffffu, rm0, 1));
        rm0 = fmaxf(rm0, __shfl_xor_sync(0xffffffffu, rm0, 2));
        rm1 = fmaxf(rm1, __shfl_xor_sync(0xffffffffu, rm1, 1));
        rm1 = fmaxf(rm1, __shfl_xor_sync(0xffffffffu, rm1, 2));
        float m0n = fmaxf(m0, rm0), m1n = fmaxf(m1, rm1);
        float r0 = fexp(m0 - m0n), r1 = fexp(m1 - m1n);
        float ls0 = 0.f, ls1 = 0.f;
        #pragma unroll
        for (int ni = 0; ni < 8; ni++){
            S_[ni][0] = fexp(S_[ni][0] - m0n);
            S_[ni][1] = fexp(S_[ni][1] - m0n);
            S_[ni][2] = fexp(S_[ni][2] - m1n);
            S_[ni][3] = fexp(S_[ni][3] - m1n);
            ls0 += S_[ni][0] + S_[ni][1];
            ls1 += S_[ni][2] + S_[ni][3];
            Oa[ni][0] *= r0; Oa[ni][1] *= r0;
            Oa[ni][2] *= r1; Oa[ni][3] *= r1;
        }
        ls0 += __shfl_xor_sync(0xffffffffu, ls0, 1);
        ls0 += __shfl_xor_sync(0xffffffffu, ls0, 2);
        ls1 += __shfl_xor_sync(0xffffffffu, ls1, 1);
        ls1 += __shfl_xor_sync(0xffffffffu, ls1, 2);
        l0 = l0*r0 + ls0;
        l1 = l1*r1 + ls1;
        m0 = m0n; m1 = m1n;

        // ---- O += P @ V (fp16x3, P hi/lo from registers) ----
        #pragma unroll
        for (int kk = 0; kk < 4; kk++){
            unsigned h0,l0w,h1,l1w,h2,l2w,h3,l3w;
            split2(S_[2*kk  ][0], S_[2*kk  ][1], h0, l0w);   // row g,  k 2q..2q+1
            split2(S_[2*kk  ][2], S_[2*kk  ][3], h1, l1w);   // row g+8
            split2(S_[2*kk+1][0], S_[2*kk+1][1], h2, l2w);   // row g,  k 2q+8..2q+9
            split2(S_[2*kk+1][2], S_[2*kk+1][3], h3, l3w);   // row g+8
            #pragma unroll
            for (int ni = 0; ni < 8; ni++){
                uint4 bb = *(const uint4*)&skv[4096 + (ni*8+g)*64 + kk*16 + 4*q];
                mma_f16(Oa[ni], h0, h1, h2, h3, bb.x, bb.z);
                mma_f16(Oa[ni], h0, h1, h2, h3, bb.y, bb.w);
                mma_f16(Oa[ni], l0w, l1w, l2w, l3w, bb.x, bb.z);
            }
        }
        __syncthreads();   // smem reads done before next tile overwrites
    }

    // ---- finalize: divide by l, write HL natural (token row, col h*64+c) ----
    float i0 = 1.f / l0, i1 = 1.f / l1;
    long long rg  = (tokB + qrow_g ) * DM;
    long long rg8 = (tokB + qrow_g8) * DM;
    #pragma unroll
    for (int ni = 0; ni < 8; ni++){
        int c = ni*8 + 2*q;
        int w = hlw(h*32 + (c >> 1));
        unsigned hh, ll;
        split2(Oa[ni][0]*i0, Oa[ni][1]*i0, hh, ll);
        *(uint2*)&O[rg + w]  = make_uint2(hh, ll);
        split2(Oa[ni][2]*i1, Oa[ni][3]*i1, hh, ll);
        *(uint2*)&O[rg8 + w] = make_uint2(hh, ll);
    }
}

// ---------------- fp16x3 GEMM on HL operands ----------------
template<int NTILES>
__global__ __launch_bounds__(256,2) void gemm_hh_kernel(
    const unsigned* __restrict__ A, const unsigned* __restrict__ B,
    float* __restrict__ Cf, unsigned* __restrict__ Ch,
    int M, int N, int K, int ldaw, int ldbw, int ldc,
    int innerN,
    long long sAo, long long sAi, long long sBo, long long sBi,
    long long sCo, long long sCi,
    const int* __restrict__ rowIdx, const int* __restrict__ tileExpert,
    long long expSB, float alpha, int actMode, int cT,
    MD md, int nMulti,
    const int* __restrict__ moeOff, const int* __restrict__ moeCnt)
{
    __shared__ unsigned As[3][128][16];
    __shared__ unsigned Bs[3][NTILES*16][16];

    int z  = blockIdx.z;
    int zo = z / innerN, zi = z - zo*innerN;
    if (nMulti > 0){
        A = md.a[zi];
        Cf = md.f[zi]; Ch = md.h[zi];
        ldc = md.ldc[zi]; cT = md.cT[zi];
    }
    const int tm0 = blockIdx.y * 128;
    const int tn0 = blockIdx.x * (NTILES*16);
    if (moeCnt){
        int e = tileExpert[blockIdx.y];
        if (tm0 >= moeOff[e] + moeCnt[e]) return;
    }
    A += zo*sAo + zi*sAi;
    long long boff = zo*sBo + zi*sBi;
    if (tileExpert) boff += (long long)tileExpert[blockIdx.y] * expSB;
    B += boff;
    long long coff = zo*sCo + zi*sCi;

    const int tid = threadIdx.x;
    const int lane = tid & 31;
    const int warp = tid >> 5;
    const int wm = (warp & 3) * 32;
    const int wn = (warp >> 2) * (NTILES*8);
    const int g = lane >> 2;
    const int q = lane & 3;

    const int lrow = tid >> 1;
    const int lsel = tid & 1;
    int grow = tm0 + lrow;
    bool aval = grow < M;
    int srcRow = aval ? (rowIdx ? (rowIdx[grow] & (NTOK-1)) : grow) : 0;
    const unsigned* Ap = A + (long long)srcRow * ldaw + lsel*8;
    unsigned aS = (unsigned)__cvta_generic_to_shared(&As[0][0][0])
                  + (unsigned)((lrow*16 + lsel*8)*4);

    const int tprB = 256/(NTILES*16);
    const int bwords = 16/tprB;
    const int browL = tid / tprB;
    const int bseg = tid % tprB;
    bool bval = (tn0 + browL) < N;
    int brow = bval ? (tn0 + browL) : 0;
    const unsigned* Bp = B + (long long)brow * ldbw + bseg*bwords;
    unsigned bS = (unsigned)__cvta_generic_to_shared(&Bs[0][0][0])
                  + (unsigned)((browL*16 + bseg*bwords)*4);
    const unsigned bStage = (unsigned)(NTILES*16*16*4);

    float acc[2][NTILES][4];
    #pragma unroll
    for (int mi=0;mi<2;mi++)
        #pragma unroll
        for (int ni=0;ni<NTILES;ni++)
            #pragma unroll
            for (int t=0;t<4;t++) acc[mi][ni][t]=0.f;

    const int nt = K >> 4;

    #define ISSUE_AT(T, ST) do{                                   \
        int _t = (T);                                              \
        if (_t < nt){                                              \
            unsigned _boA = (unsigned)((ST) * 8192);               \
            unsigned _boB = (unsigned)(ST) * bStage;               \
            int _kn = _t * 16;                                     \
            cp16(aS + _boA,      Ap + _kn,     aval);              \
            cp16(aS + _boA + 16, Ap + _kn + 4, aval);              \
            cp16(bS + _boB,      Bp + _kn,     bval);              \
            if (bwords == 8)                                       \
                cp16(bS + _boB + 16, Bp + _kn + 4, bval);          \
        }                                                          \
        asm volatile("cp.async.commit_group;");                    \
    }while(0)

    ISSUE_AT(0, 0);
    ISSUE_AT(1, 1);

    int buf = 0, fill = 2;
    for (int k = 0; k < nt; k++){
        asm volatile("cp.async.wait_group 1;");
        __syncthreads();
        ISSUE_AT(k+2, fill);
        {
            uint4 a1[2], a2[2];
            #pragma unroll
            for (int mi = 0; mi < 2; mi++){
                int row = wm + mi*16 + g;
                a1[mi] = *(const uint4*)&As[buf][row  ][4*q];
                a2[mi] = *(const uint4*)&As[buf][row+8][4*q];
            }
            #pragma unroll
            for (int ni = 0; ni < NTILES; ni++){
                int col = wn + ni*8 + g;
                uint4 bb = *(const uint4*)&Bs[buf][col][4*q];
                #pragma unroll
                for (int mi = 0; mi < 2; mi++){
                    mma_f16(acc[mi][ni], a1[mi].x, a2[mi].x, a1[mi].z, a2[mi].z, bb.x, bb.z);
                    mma_f16(acc[mi][ni], a1[mi].x, a2[mi].x, a1[mi].z, a2[mi].z, bb.y, bb.w);
                    mma_f16(acc[mi][ni], a1[mi].y, a2[mi].y, a1[mi].w, a2[mi].w, bb.x, bb.z);
                }
            }
        }
        buf  = (buf  == 2) ? 0 : buf  + 1;
        fill = (fill == 2) ? 0 : fill + 1;
    }
    #undef ISSUE_AT

    float* CfP = Cf ? (Cf + coff) : (float*)0;
    unsigned* ChP = Ch ? (Ch + coff) : (unsigned*)0;
    #pragma unroll
    for (int mi = 0; mi < 2; mi++){
        #pragma unroll
        for (int rr = 0; rr < 2; rr++){
            int row = tm0 + wm + mi*16 + g + rr*8;
            if (row >= M) continue;
            #pragma unroll
            for (int ni = 0; ni < NTILES; ni++){
                int col = tn0 + wn + ni*8 + q*2;
                if (col >= N) continue;
                float v0 = acc[mi][ni][rr*2+0] * alpha;
                float v1 = acc[mi][ni][rr*2+1] * alpha;
                if (actMode == 1){
                    v0 = 0.5f * v0 * (1.f + erff(v0 * 0.70710678118654752f));
                    v1 = 0.5f * v1 * (1.f + erff(v1 * 0.70710678118654752f));
                }
                if (!cT){
                    if (CfP) *(float2*)&CfP[(long long)row*ldc + col] = make_float2(v0, v1);
                    if (ChP){
                        unsigned h,l; split2(v0,v1,h,l);
                        *(uint2*)&ChP[(long long)row*ldc + hlw(col>>1)] = make_uint2(h,l);
                    }
                } else {
                    int W = hlw(row >> 1);
                    int hs = row & 1;
                    {
                        __half h0 = __float2half_rn(v0);
                        unsigned* p = ChP + (long long)col*ldc;
                        ((__half*)(p + W    ))[hs] = h0;
                        ((__half*)(p + W + 1))[hs] = __float2half_rn(v0 - __half2float(h0));
                    }
                    if (col + 1 < N){
                        __half h1 = __float2half_rn(v1);
                        unsigned* p = ChP + (long long)(col+1)*ldc;
                        ((__half*)(p + W    ))[hs] = h1;
                        ((__half*)(p + W + 1))[hs] = __float2half_rn(v1 - __half2float(h1));
                    }
                }
            }
        }
    }
}

// ---------------- delta branch ----------------
__global__ __launch_bounds__(256) void ctx1_kernel(const float* __restrict__ kd,
                                                   const float* __restrict__ vd,
                                                   float* __restrict__ ctxp,
                                                   float* __restrict__ ksump){
    int z = blockIdx.x >> 2;
    int chunk = blockIdx.x & 3;
    int b = z >> 4, h = z & 15;
    const float* kbase = kd + ((long long)b*SEQ)*DM + h*DK;
    const float* vbase = vd + ((long long)b*SEQ)*DM + h*DK;
    __shared__ float ks[64][65];
    __shared__ float vs[64][65];
    int tid = threadIdx.x;
    int d0 = (tid >> 4) << 2;
    int e0 = (tid & 15) << 2;
    float acc[4][4];
    #pragma unroll
    for (int i=0;i<4;i++)
        #pragma unroll
        for (int j=0;j<4;j++) acc[i][j]=0.f;
    float ksacc = 0.f;

    for (int s0 = chunk*256; s0 < chunk*256+256; s0 += 64) {
        for (int t = tid; t < 64*16; t += 256) {
            int rr = t >> 4; int cc = (t & 15) << 2;
            float4 kv = *(const float4*)(kbase + (long long)(s0+rr)*DM + cc);
            float4 vv = *(const float4*)(vbase + (long long)(s0+rr)*DM + cc);
            ks[rr][cc+0]=kv.x; ks[rr][cc+1]=kv.y; ks[rr][cc+2]=kv.z; ks[rr][cc+3]=kv.w;
            vs[rr][cc+0]=vv.x; vs[rr][cc+1]=vv.y; vs[rr][cc+2]=vv.z; vs[rr][cc+3]=vv.w;
        }
        __syncthreads();
        if (tid < DK){
            #pragma unroll 8
            for (int rr=0; rr<64; rr++) ksacc += fmaxf(ks[rr][tid], 0.f);
        }
        #pragma unroll 4
        for (int ss=0; ss<64; ss++){
            float kr[4], vr[4];
            #pragma unroll
            for (int i=0;i<4;i++) kr[i]=ks[ss][d0+i];
            #pragma unroll
            for (int j=0;j<4;j++) vr[j]=vs[ss][e0+j];
            #pragma unroll
            for (int i=0;i<4;i++)
                #pragma unroll
                for (int j=0;j<4;j++) acc[i][j] += kr[i]*vr[j];
        }
        __syncthreads();
    }
    float* cbase = ctxp + ((long long)z*4 + chunk)*DK*DK;
    #pragma unroll
    for (int i=0;i<4;i++)
        #pragma unroll
        for (int j=0;j<4;j++)
            cbase[(d0+i)*DK + e0+j] = acc[i][j];
    if (tid < DK) ksump[((long long)z*4 + chunk)*DK + tid] = ksacc;
}

__global__ void ctx2_kernel(const float* __restrict__ ctxp, float* __restrict__ ctx,
                            const float* __restrict__ ksump, float* __restrict__ ksum){
    int z = blockIdx.x;
    const float* p = ctxp + (long long)z*4*DK*DK;
    float* o = ctx + (long long)z*DK*DK;
    for (int i = threadIdx.x; i < DK*DK; i += 256)
        o[i] = p[i] + p[DK*DK + i] + p[2*DK*DK + i] + p[3*DK*DK + i];
    if (threadIdx.x < DK){
        int d = threadIdx.x;
        float s = 0.f;
        #pragma unroll
        for (int c=0;c<4;c++) s += ksump[((long long)z*4 + c)*DK + d];
        ksum[z*DK + d] = s;
    }
}

__global__ __launch_bounds__(256) void delta_kernel(const float* __restrict__ qd,
                                                    const float* __restrict__ ctx,
                                                    const float* __restrict__ ksum,
                                                    unsigned* __restrict__ du){
    int z = blockIdx.x >> 2;
    int sc = blockIdx.x & 3;
    int b = z >> 4, h = z & 15;
    __shared__ float cs[DK*DK];
    __shared__ float kss[DK];
    for (int i = threadIdx.x; i < DK*DK; i += 256) cs[i] = ctx[(long long)z*DK*DK + i];
    if (threadIdx.x < DK) kss[threadIdx.x] = ksum[z*DK + threadIdx.x];
    __syncthreads();
    int s = sc*256 + threadIdx.x;
    const float* qrow = qd + ((long long)(b*SEQ + s))*DM + h*DK;
    float q[DK];
    #pragma unroll
    for (int d=0; d<DK; d+=4){
        float4 v = *(const float4*)(qrow + d);
        q[d+0]=fmaxf(v.x,0.f); q[d+1]=fmaxf(v.y,0.f);
        q[d+2]=fmaxf(v.z,0.f); q[d+3]=fmaxf(v.w,0.f);
    }
    float zv = 1e-6f;
    #pragma unroll
    for (int d=0; d<DK; d++) zv += q[d]*kss[d];
    float invz = 1.f / zv;
    unsigned* ob = du + ((long long)(b*SEQ + s))*DM + h*DK;
    for (int e=0; e<DK; e+=2){
        float a0 = 0.f, a1 = 0.f;
        #pragma unroll
        for (int d=0; d<DK; d++){
            a0 += q[d]*cs[d*DK + e];
            a1 += q[d]*cs[d*DK + e+1];
        }
        unsigned hh,ll; split2(a0*invz, a1*invz, hh, ll);
        *(uint2*)&ob[hlw(e>>1)] = make_uint2(hh,ll);
    }
}

// ---------------- router / moe plumbing / final ----------------
__device__ __forceinline__ float warpSumR(float v){
    #pragma unroll
    for (int o=16;o;o>>=1) v += __shfl_xor_sync(0xffffffffu, v, o);
    return v;
}
__global__ __launch_bounds__(256) void router_kernel(const float* __restrict__ xn2,
                                                     const float* __restrict__ wr,
                                                     int* __restrict__ topk_idx,
                                                     float* __restrict__ topk_w,
                                                     int* __restrict__ counts){
    int t = blockIdx.x;
    float p[NE];
    #pragma unroll
    for (int e=0;e<NE;e++) p[e]=0.f;
    for (int k = threadIdx.x; k < DM; k += 256){
        float xv = xn2[(long long)t*DM + k];
        #pragma unroll
        for (int e=0;e<NE;e++) p[e] += xv*wr[k*NE + e];
    }
    __shared__ float part[NE][8];
    int w = threadIdx.x >> 5;
    #pragma unroll
    for (int e=0;e<NE;e++){
        float v = warpSumR(p[e]);
        if ((threadIdx.x & 31)==0) part[e][w] = v;
    }
    __syncthreads();
    if (threadIdx.x == 0){
        float lg[NE];
        for (int e=0;e<NE;e++){
            float s=0.f;
            for (int ww=0; ww<8; ww++) s += part[e][ww];
            lg[e]=s;
        }
        int i0=0; float v0=lg[0];
        for (int e=1;e<NE;e++) if (lg[e]>v0){v0=lg[e];i0=e;}
        int i1=-1; float v1=-3.0e38f;
        for (int e=0;e<NE;e++) if (e!=i0 && lg[e]>v1){v1=lg[e];i1=e;}
        float e1 = expf(v1-v0);
        float inv = 1.f/(1.f+e1);
        topk_idx[t*2+0]=i0; topk_idx[t*2+1]=i1;
        topk_w[t*2+0]=inv;  topk_w[t*2+1]=e1*inv;
        atomicAdd(&counts[i0],1); atomicAdd(&counts[i1],1);
    }
}

__global__ void prep_kernel(int* counts, int* cursor, int* tok){
    int i = blockIdx.x*256 + threadIdx.x;
    if (i < NE){ counts[i]=0; cursor[i]=0; }
    if (i < PAIR_CAP) tok[i]=0;
}

__global__ void scan_kernel(const int* counts, int* off, int* tile_e){
    if (threadIdx.x==0 && blockIdx.x==0){
        int o = 0;
        off[0]=0;
        for (int e=0;e<NE;e++){ o += (counts[e]+127)&~127; off[e+1]=o; }
        for (int t=0;t<NTILE72;t++){
            int row = t*128;
            int ee = NE-1;
            for (int i=0;i<NE;i++){ if (row < off[i+1]) { ee=i; break; } }
            tile_e[t]=ee;
        }
    }
}

__global__ void place_kernel(const int* __restrict__ topk_idx,
                             const int* __restrict__ off,
                             int* cursor, int* tok, int* pair_pos){
    int t = blockIdx.x*256 + threadIdx.x;
    if (t >= NTOK) return;
    for (int k=0;k<2;k++){
        int e = topk_idx[t*2+k];
        int pos = atomicAdd(&cursor[e],1);
        int r = off[e] + pos;
        tok[r] = t;
        pair_pos[t*2+k] = r;
    }
}

__global__ void final_kernel(const float* __restrict__ x1,
                             const float* __restrict__ y2,
                             const float* __restrict__ topk_w,
                             const int* __restrict__ pair_pos,
                             float* __restrict__ out){
    long long i = ((long long)blockIdx.x*256 + threadIdx.x) * 4;
    int t = (int)(i >> 10);
    int c = (int)(i & 1023);
    float w0 = topk_w[t*2+0], w1 = topk_w[t*2+1];
    long long b0 = (long long)pair_pos[t*2+0]*DM + c;
    long long b1 = (long long)pair_pos[t*2+1]*DM + c;
    float4 a  = *(const float4*)&x1[i];
    float4 y0 = *(const float4*)&y2[b0];
    float4 y1 = *(const float4*)&y2[b1];
    float4 r;
    r.x = a.x + w0*y0.x + w1*y1.x;
    r.y = a.y + w0*y0.y + w1*y1.y;
    r.z = a.z + w0*y0.z + w1*y1.z;
    r.w = a.w + w0*y0.w + w1*y1.w;
    *(float4*)&out[i] = r;
}

// ---------------- host side ----------------
static void gemm(const unsigned* A, const unsigned* B,
                 float* Cf, unsigned* Ch,
                 int M, int N, int K, int ldaw, int ldbw, int ldc,
                 int batch, int innerN,
                 long long sAo, long long sAi, long long sBo, long long sBi,
                 long long sCo, long long sCi,
                 const int* rowIdx, const int* tileE, long long expSB,
                 float alpha, int act, int cT,
                 const MD& md, int nMulti,
                 const int* moeOff, const int* moeCnt){
    dim3 grid((N+127)/128, (M+127)/128, batch);
    gemm_hh_kernel<8><<<grid, 256>>>(A,B,Cf,Ch,M,N,K,ldaw,ldbw,ldc,innerN,
                                     sAo,sAi,sBo,sBi,sCo,sCi,
                                     rowIdx,tileE,expSB,alpha,act,cT,md,nMulti,
                                     moeOff,moeCnt);
}

extern "C" void kernel_launch(void* const* d_in, const int* in_sizes, int n_in,
                              void* d_out, int out_size){
    const float* x        = (const float*)d_in[0];
    const int*   mask     = (const int*)  d_in[1];
    const float* ln1_g    = (const float*)d_in[2];
    const float* ln1_b    = (const float*)d_in[3];
    const float* wq       = (const float*)d_in[4];
    const float* wk       = (const float*)d_in[5];
    const float* wv       = (const float*)d_in[6];
    const float* wo       = (const float*)d_in[7];
    const float* wqd      = (const float*)d_in[8];
    const float* wkd      = (const float*)d_in[9];
    const float* wvd      = (const float*)d_in[10];
    const float* wod      = (const float*)d_in[11];
    const float* w_gate   = (const float*)d_in[12];
    const float* ln2_g    = (const float*)d_in[13];
    const float* ln2_b    = (const float*)d_in[14];
    const float* w_router = (const float*)d_in[15];
    const float* e_w1     = (const float*)d_in[16];
    const float* e_w2     = (const float*)d_in[17];
    float* out = (float*)d_out;

    float *xn1,*qd,*kd,*vd,*dense_o,*delta_o,*x1,*xn2,*ctx,*ctxp,*ksum,*ksump,*y2,*topk_w;
    int *topk_idx,*counts,*cursor,*off,*tile_e,*tok,*pair_pos;
    unsigned *xn1u,*qu,*ku,*vTu,*actu,*dlu,*xn2u,*h1u,*wu,*e1u,*e2u,*mb;

    cudaGetSymbolAddress((void**)&xn1,     g_xn1);
    cudaGetSymbolAddress((void**)&qd,      g_qd);
    cudaGetSymbolAddress((void**)&kd,      g_kd);
    cudaGetSymbolAddress((void**)&vd,      g_vd);
    cudaGetSymbolAddress((void**)&dense_o, g_dense_o);
    cudaGetSymbolAddress((void**)&delta_o, g_delta_o);
    cudaGetSymbolAddress((void**)&x1,      g_x1);
    cudaGetSymbolAddress((void**)&xn2,     g_xn2);
    cudaGetSymbolAddress((void**)&ctx,     g_ctx);
    cudaGetSymbolAddress((void**)&ctxp,    g_ctxp);
    cudaGetSymbolAddress((void**)&ksum,    g_ksum);
    cudaGetSymbolAddress((void**)&ksump,   g_ksump);
    cudaGetSymbolAddress((void**)&y2,      g_y2);
    cudaGetSymbolAddress((void**)&topk_w,  g_topk_w);
    cudaGetSymbolAddress((void**)&topk_idx,g_topk_idx);
    cudaGetSymbolAddress((void**)&counts,  g_counts);
    cudaGetSymbolAddress((void**)&cursor,  g_cursor);
    cudaGetSymbolAddress((void**)&off,     g_off);
    cudaGetSymbolAddress((void**)&tile_e,  g_tile_e);
    cudaGetSymbolAddress((void**)&tok,     g_tok);
    cudaGetSymbolAddress((void**)&pair_pos,g_pair_pos);
    cudaGetSymbolAddress((void**)&xn1u,    g_xn1u);
    cudaGetSymbolAddress((void**)&qu,      g_qu);
    cudaGetSymbolAddress((void**)&ku,      g_ku);
    cudaGetSymbolAddress((void**)&vTu,     g_vTu);
    cudaGetSymbolAddress((void**)&actu,    g_actu);
    cudaGetSymbolAddress((void**)&dlu,     g_dlu);
    cudaGetSymbolAddress((void**)&xn2u,    g_xn2u);
    cudaGetSymbolAddress((void**)&h1u,     g_h1u);
    cudaGetSymbolAddress((void**)&wu,      g_wu);
    cudaGetSymbolAddress((void**)&e1u,     g_e1u);
    cudaGetSymbolAddress((void**)&e2u,     g_e2u);
    cudaGetSymbolAddress((void**)&mb,      g_mb);

    MD md0; memset(&md0, 0, sizeof(md0));

    // 0: LN1
    ln_kernel<<<NTOK,256>>>(x, ln1_g, ln1_b, xn1, xn1u);
    // 1: dense weight splits
    WP8 wp;
    wp.p[0]=wq; wp.p[1]=wk; wp.p[2]=wv; wp.p[3]=wqd;
    wp.p[4]=wkd; wp.p[5]=wvd; wp.p[6]=wo; wp.p[7]=wod;
    wsplit8_kernel<<<dim3(32,32,8), dim3(32,8)>>>(wp, wu);
    // 2: mask bit-pack
    maskpack_kernel<<<NB*SEQ*4, 256>>>(mask, mb);

    // 3: all 6 projections (batched)
    {
        MD md; memset(&md, 0, sizeof(md));
        for (int z=0; z<6; z++){ md.a[z]=xn1u; md.ldc[z]=DM; md.cT[z]=0; }
        md.h[0]=qu;
        md.h[1]=ku;
        md.h[2]=vTu; md.ldc[2]=NTOK; md.cT[2]=1;
        md.f[3]=qd;
        md.f[4]=kd;
        md.f[5]=vd;
        gemm(xn1u, wu, 0,0,
             NTOK,DM,DM, DM,DM,DM, 6,6,
             0,0, 0,WSZ, 0,0,
             0,0,0, 1.f,0,0, md, 6, 0,0);
    }

    // 4: fused flash attention -> actu (HL natural)
    fattn_kernel<<<dim3(SEQ/128, NB*NH), 256>>>(qu, ku, vTu, mb, actu);

    // delta branch (ksum fused)
    ctx1_kernel<<<NB*NH*4, 256>>>(kd, vd, ctxp, ksump);
    ctx2_kernel<<<NB*NH, 256>>>(ctxp, ctx, ksump, ksum);
    delta_kernel<<<NB*NH*4, 256>>>(qd, ctx, ksum, dlu);

    // output projections, batched 2
    {
        MD md; memset(&md, 0, sizeof(md));
        md.a[0]=actu; md.f[0]=dense_o; md.ldc[0]=DM; md.cT[0]=0;
        md.a[1]=dlu;  md.f[1]=delta_o; md.ldc[1]=DM; md.cT[1]=0;
        gemm(actu, wu+6LL*WSZ, 0,0,
             NTOK,DM,DM, DM,DM,DM, 2,2,
             0,0, 0,WSZ, 0,0,
             0,0,0, 1.f,0,0, md, 2, 0,0);
    }

    // fused gate + combine + LN2
    combine_ln_kernel<<<NTOK,256>>>(x, dense_o, delta_o, xn1, w_gate,
                                    ln2_g, ln2_b, x1, xn2, xn2u);

    // routing
    prep_kernel<<<(PAIR_CAP+255)/256, 256>>>(counts, cursor, tok);
    router_kernel<<<NTOK, 256>>>(xn2, w_router, topk_idx, topk_w, counts);
    scan_kernel<<<1,32>>>(counts, off, tile_e);
    place_kernel<<<(NTOK+255)/256, 256>>>(topk_idx, off, cursor, tok, pair_pos);

    // expert weight splits
    wsplit_kernel<<<dim3(DFF/32, DM/32, NE), dim3(32,8)>>>(e_w1, e1u, DM, DFF);

    // expert GEMM1 (gathered, gelu) -> h1 HL ; pad tiles skipped
    gemm(xn2u, e1u, 0,h1u, PAIR_CAP,DFF,DM, DM,DM,DFF,
         1,1, 0,0,0,0,0,0,
         tok, tile_e, (long long)DM*DFF, 1.f,1,0, md0, 0, off, counts);

    wsplit_kernel<<<dim3(DM/32, DFF/32, NE), dim3(32,8)>>>(e_w2, e2u, DFF, DM);

    // expert GEMM2 -> y2 fp32 ; pad tiles skipped
    gemm(h1u, e2u, y2,0, PAIR_CAP,DM,DFF, DFF,DFF,DM,
         1,1, 0,0,0,0,0,0,
         0, tile_e, (long long)DFF*DM, 1.f,0,0, md0, 0, off, counts);

    // final combine (float4)
    final_kernel<<<NTOK*DM/1024, 256>>>(x1, y2, topk_w, pair_pos, out);
}

// round 16
// speedup vs baseline: 1.1263x; 1.0143x over previous
#include <cuda_runtime.h>
#include <cuda_fp16.h>
#include <math.h>

#define NTOK 4096
#define DM   1024
#define DFF  2048
#define NH   16
#define DK   64
#define NB   4
#define SEQ  1024
#define NE   8
#define PAIR_CAP 9216
#define NTILE72  72
#define WSZ  (1024*1024)

// ---------------- fp32 scratch ----------------
__device__ float g_qd [NTOK*DM];
__device__ float g_kd [NTOK*DM];
__device__ float g_vd [NTOK*DM];
__device__ float g_dense_o[NTOK*DM];
__device__ float g_delta_o[NTOK*DM];
__device__ float g_x1 [NTOK*DM];
__device__ float g_xn1[NTOK*DM];
__device__ float g_xn2[NTOK*DM];
__device__ float g_ctx [NB*NH*DK*DK];
__device__ float g_ctxp[NB*NH*4*DK*DK];
__device__ float g_ksum[NB*NH*DK];
__device__ float g_ksump[NB*NH*4*DK];
__device__ float g_y2[(long long)PAIR_CAP*DM];
__device__ int   g_topk_idx[NTOK*2];
__device__ float g_topk_w [NTOK*2];
__device__ int   g_counts[NE];
__device__ int   g_cursor[NE];
__device__ int   g_off[NE+1];
__device__ int   g_tile_e[NTILE72];
__device__ int   g_tok[PAIR_CAP];
__device__ int   g_pair_pos[NTOK*2];
__device__ unsigned g_mb[NB*SEQ*32];     // packed mask bits

// ---------------- HL scratch ----------------
__device__ unsigned g_xn1u[NTOK*DM];
__device__ unsigned g_qu  [NTOK*DM];
__device__ unsigned g_ku  [NTOK*DM];
__device__ unsigned g_vTu [DM*NTOK];
__device__ unsigned g_actu[NTOK*DM];
__device__ unsigned g_dlu [NTOK*DM];
__device__ unsigned g_xn2u[NTOK*DM];
__device__ unsigned g_h1u [(long long)PAIR_CAP*DFF];
__device__ unsigned g_wu  [8LL*WSZ];
__device__ unsigned g_e1u [8LL*DM*DFF];
__device__ unsigned g_e2u [8LL*DFF*DM];

struct MD {
    const unsigned* a[6];
    float* f[6]; unsigned* h[6];
    int ldc[6]; int cT[6];
};

// ---------------- perm helpers ----------------
__device__ __forceinline__ int pperm(int p){ return ((p&3)<<1) | (p>>2); }
__device__ __forceinline__ int hlw(int p){ return 2*(p & ~7) + 2*pperm(p & 7); }

// ---------------- low-level ----------------
__device__ __forceinline__ void mma_f16(float* d,
        unsigned a0, unsigned a1, unsigned a2, unsigned a3,
        unsigned b0, unsigned b1){
    asm volatile("mma.sync.aligned.m16n8k16.row.col.f32.f16.f16.f32 "
        "{%0,%1,%2,%3}, {%4,%5,%6,%7}, {%8,%9}, {%0,%1,%2,%3};"
        : "+f"(d[0]),"+f"(d[1]),"+f"(d[2]),"+f"(d[3])
        : "r"(a0),"r"(a1),"r"(a2),"r"(a3),"r"(b0),"r"(b1));
}
__device__ __forceinline__ unsigned packh(__half x, __half y){
    return (unsigned)__half_as_ushort(x) | ((unsigned)__half_as_ushort(y) << 16);
}
__device__ __forceinline__ void split2(float x, float y, unsigned& hi, unsigned& lo){
    __half hx = __float2half_rn(x), hy = __float2half_rn(y);
    __half lx = __float2half_rn(x - __half2float(hx));
    __half ly = __float2half_rn(y - __half2float(hy));
    hi = packh(hx, hy);
    lo = packh(lx, ly);
}
__device__ __forceinline__ void cp16(unsigned saddr, const void* g, bool v){
    asm volatile("cp.async.ca.shared.global [%0], [%1], 16, %2;"
        :: "r"(saddr), "l"(g), "r"(v ? 16 : 0));
}
__device__ __forceinline__ float fexp(float v){
    float y = v * 1.4426950408889634f;
    y = fmaxf(y, -126.0f);
    float n = floorf(y);
    float f = y - n;
    float p = 1.5403530e-4f;
    p = fmaf(p, f, 1.3333558e-3f);
    p = fmaf(p, f, 9.6181291e-3f);
    p = fmaf(p, f, 5.5504109e-2f);
    p = fmaf(p, f, 2.4022651e-1f);
    p = fmaf(p, f, 6.9314718e-1f);
    p = fmaf(p, f, 1.0f);
    return __int_as_float(((int)n + 127) << 23) * p;
}

__device__ __forceinline__ float warpSum(float v){
    #pragma unroll
    for (int o=16;o;o>>=1) v += __shfl_xor_sync(0xffffffffu, v, o);
    return v;
}
__device__ __forceinline__ float blockSum(float v, float* red){
    v = warpSum(v);
    if ((threadIdx.x & 31) == 0) red[threadIdx.x>>5] = v;
    __syncthreads();
    if (threadIdx.x < 32) {
        float t = (threadIdx.x < 8) ? red[threadIdx.x] : 0.f;
        t = warpSum(t);
        if (threadIdx.x == 0) red[0] = t;
    }
    __syncthreads();
    float r = red[0];
    __syncthreads();
    return r;
}

// ---------------- weight transpose + split -> HL ----------------
struct WP8 { const float* p[8]; };

__global__ void wsplit8_kernel(WP8 wp, unsigned* __restrict__ oB){
    __shared__ float ts[32][33];
    int mat = blockIdx.z;
    const float* W = wp.p[mat];
    unsigned* o = oB + (long long)mat*WSZ;
    int k0 = blockIdx.y*32, n0 = blockIdx.x*32;
    int tx = threadIdx.x, ty = threadIdx.y;
    #pragma unroll
    for (int i=0;i<4;i++)
        ts[ty+8*i][tx] = W[(long long)(k0+ty+8*i)*DM + n0 + tx];
    __syncthreads();
    int tid = ty*32 + tx;
    #pragma unroll
    for (int it=0; it<2; it++){
        int item = it*256 + tid;
        int n = item >> 4;
        int pr = item & 15;
        unsigned h,l; split2(ts[2*pr][n], ts[2*pr+1][n], h, l);
        *(uint2*)&o[(long long)(n0+n)*DM + hlw((k0>>1)+pr)] = make_uint2(h,l);
    }
}

__global__ void wsplit_kernel(const float* __restrict__ W,
                              unsigned* __restrict__ o, int K, int N){
    __shared__ float ts[32][33];
    W += (long long)blockIdx.z * K * N;
    o += (long long)blockIdx.z * K * N;
    int k0 = blockIdx.y*32, n0 = blockIdx.x*32;
    int tx = threadIdx.x, ty = threadIdx.y;
    #pragma unroll
    for (int i=0;i<4;i++)
        ts[ty+8*i][tx] = W[(long long)(k0+ty+8*i)*N + n0 + tx];
    __syncthreads();
    int tid = ty*32 + tx;
    #pragma unroll
    for (int it=0; it<2; it++){
        int item = it*256 + tid;
        int n = item >> 4;
        int pr = item & 15;
        unsigned h,l; split2(ts[2*pr][n], ts[2*pr+1][n], h, l);
        *(uint2*)&o[(long long)(n0+n)*K + hlw((k0>>1)+pr)] = make_uint2(h,l);
    }
}

// ---------------- layernorm (fp32 + HL out, optional mask bit-pack) ----------------
__global__ __launch_bounds__(256) void ln_kernel(const float* __restrict__ x,
                                                 const float* __restrict__ g,
                                                 const float* __restrict__ b,
                                                 float* __restrict__ y,
                                                 unsigned* __restrict__ yu,
                                                 const int* __restrict__ mask,
                                                 unsigned* __restrict__ mb){
    __shared__ float row[DM];
    __shared__ float red[8];
    long long base = (long long)blockIdx.x * DM;
    // fold mask bit-pack into LN1 (one mask row per token block)
    if (mask){
        int warp = threadIdx.x >> 5, lane = threadIdx.x & 31;
        const int* mrow = mask + base;     // same row index: [b*SEQ+q]*1024
        #pragma unroll
        for (int w0 = warp; w0 < 32; w0 += 8){
            unsigned bits = __ballot_sync(0xffffffffu, mrow[w0*32 + lane] != 0);
            if (lane == 0) mb[blockIdx.x*32 + w0] = bits;
        }
    }
    float s = 0.f;
    for (int i = threadIdx.x; i < DM; i += 256) { float v = x[base+i]; row[i] = v; s += v; }
    s = blockSum(s, red);
    float mu = s * (1.f/DM);
    float vs = 0.f;
    for (int i = threadIdx.x; i < DM; i += 256) { float d = row[i]-mu; vs += d*d; }
    vs = blockSum(vs, red);
    float rstd = rsqrtf(vs * (1.f/DM) + 1e-5f);
    unsigned* ob = yu + base;
    for (int i2 = threadIdx.x; i2 < DM/2; i2 += 256){
        int i = i2*2;
        float v0 = (row[i  ]-mu)*rstd*g[i  ] + b[i  ];
        float v1 = (row[i+1]-mu)*rstd*g[i+1] + b[i+1];
        if (y){ y[base+i] = v0; y[base+i+1] = v1; }
        unsigned h,l; split2(v0,v1,h,l);
        *(uint2*)&ob[hlw(i2)] = make_uint2(h,l);
    }
}

// ---------------- fused gate + combine + LN2 ----------------
__global__ __launch_bounds__(256) void combine_ln_kernel(
    const float* __restrict__ x, const float* __restrict__ dense,
    const float* __restrict__ delta, const float* __restrict__ xn1,
    const float* __restrict__ wg,
    const float* __restrict__ g, const float* __restrict__ b,
    float* __restrict__ x1, float* __restrict__ y, unsigned* __restrict__ yu)
{
    __shared__ float row[DM];
    __shared__ float red[8];
    long long base = (long long)blockIdx.x * DM;
    float p0=0.f, p1=0.f;
    for (int i = threadIdx.x; i < DM; i += 256){
        float xv = xn1[base+i];
        p0 += xv*wg[i*2+0];
        p1 += xv*wg[i*2+1];
    }
    p0 = blockSum(p0, red);
    p1 = blockSum(p1, red);
    float m = fmaxf(p0,p1);
    float e0 = expf(p0-m), e1 = expf(p1-m);
    float inv = 1.f/(e0+e1);
    float g0 = e0*inv, g1 = e1*inv;
    float s = 0.f;
    for (int i = threadIdx.x; i < DM; i += 256){
        float v = x[base+i] + g0*dense[base+i] + g1*delta[base+i];
        row[i] = v; x1[base+i] = v; s += v;
    }
    s = blockSum(s, red);
    float mu = s * (1.f/DM);
    float vs = 0.f;
    for (int i = threadIdx.x; i < DM; i += 256){ float d2 = row[i]-mu; vs += d2*d2; }
    vs = blockSum(vs, red);
    float rstd = rsqrtf(vs * (1.f/DM) + 1e-5f);
    unsigned* ob = yu + base;
    for (int i2 = threadIdx.x; i2 < DM/2; i2 += 256){
        int i = i2*2;
        float v0 = (row[i  ]-mu)*rstd*g[i  ] + b[i  ];
        float v1 = (row[i+1]-mu)*rstd*g[i+1] + b[i+1];
        y[base+i] = v0; y[base+i+1] = v1;
        unsigned h,l; split2(v0,v1,h,l);
        *(uint2*)&ob[hlw(i2)] = make_uint2(h,l);
    }
}

// ---------------- fused flash attention (3-buffer KV pipeline) ----------------
// grid (SEQ/128, NB*NH), 256 threads. K(t) in buf (2t)%3, V(t) in buf (2t+1)%3.
__global__ __launch_bounds__(256,2) void fattn_kernel(
    const unsigned* __restrict__ Q, const unsigned* __restrict__ Kt,
    const unsigned* __restrict__ Vt, const unsigned* __restrict__ mb,
    unsigned* __restrict__ O)
{
    __shared__ unsigned skv[12288];    // 48KB: 3 buffers x 4096 words
    const int bh = blockIdx.y;
    const int b = bh >> 4, h = bh & 15;
    const int tm0 = blockIdx.x * 128;
    const int tid = threadIdx.x;
    const int lane = tid & 31;
    const int warp = tid >> 5;
    const int g = lane >> 2;
    const int q = lane & 3;
    const long long tokB = (long long)b * SEQ;

    unsigned sb = (unsigned)__cvta_generic_to_shared(&skv[0]);

    // ---- stage Q tile (uses buffers 0..1) and read per-warp fragments ----
    #pragma unroll
    for (int j = 0; j < 8; j++){
        int w = tid*4 + j*1024;
        int row = w >> 6, col = w & 63;
        cp16(sb + w*4, Q + (tokB + tm0 + row)*DM + h*64 + col, true);
    }
    asm volatile("cp.async.commit_group;");
    asm volatile("cp.async.wait_group 0;");
    __syncthreads();
    uint4 qa[4][2];
    {
        int r0 = warp*16 + g;
        #pragma unroll
        for (int kk = 0; kk < 4; kk++){
            qa[kk][0] = *(const uint4*)&skv[r0*64      + kk*16 + 4*q];
            qa[kk][1] = *(const uint4*)&skv[(r0+8)*64  + kk*16 + 4*q];
        }
    }
    __syncthreads();

    // load helpers (4 cp16 per thread per tile)
    #define LOADK(T, BUF) do{                                                        \
        _Pragma("unroll")                                                            \
        for (int j = 0; j < 4; j++){                                                 \
            int w = tid*4 + j*1024;                                                  \
            int row = w >> 6, col = w & 63;                                          \
            cp16(sb + ((BUF)*4096 + w)*4,                                            \
                 Kt + (tokB + (T)*64 + row)*DM + h*64 + col, true);                  \
        }                                                                            \
    }while(0)
    #define LOADV(T, BUF) do{                                                        \
        _Pragma("unroll")                                                            \
        for (int j = 0; j < 4; j++){                                                 \
            int w = tid*4 + j*1024;                                                  \
            int row = w >> 6, col = w & 63;                                          \
            cp16(sb + ((BUF)*4096 + w)*4,                                            \
                 Vt + (long long)(h*64 + row)*NTOK + tokB + (T)*64 + col, true);     \
        }                                                                            \
    }while(0)

    // preload: c0 = {K0->b0, V0->b1}, c1 = {K1->b2}
    LOADK(0, 0); LOADV(0, 1);
    asm volatile("cp.async.commit_group;");
    LOADK(1, 2);
    asm volatile("cp.async.commit_group;");

    float m0 = -3.0e38f, m1 = -3.0e38f, l0 = 0.f, l1 = 0.f;
    float Oa[8][4];
    #pragma unroll
    for (int ni=0;ni<8;ni++)
        #pragma unroll
        for (int t=0;t<4;t++) Oa[ni][t] = 0.f;

    const int qrow_g  = tm0 + warp*16 + g;
    const int qrow_g8 = qrow_g + 8;
    const unsigned* mbg  = mb + ((long long)(b*SEQ + qrow_g ))*32;
    const unsigned* mbg8 = mb + ((long long)(b*SEQ + qrow_g8))*32;

    for (int kt = 0; kt < 16; kt++){
        const int bK = (2*kt) % 3;
        const int bV = (2*kt+1) % 3;
        // wait: all groups except newest done -> K(t),V(t) resident
        asm volatile("cp.async.wait_group 1;");
        __syncthreads();

        // ---- S = Q @ K^T (fp16x3) ----
        float S_[8][4];
        #pragma unroll
        for (int ni=0;ni<8;ni++)
            #pragma unroll
            for (int t=0;t<4;t++) S_[ni][t] = 0.f;
        #pragma unroll
        for (int kk = 0; kk < 4; kk++){
            #pragma unroll
            for (int ni = 0; ni < 8; ni++){
                uint4 bb = *(const uint4*)&skv[bK*4096 + (ni*8+g)*64 + kk*16 + 4*q];
                mma_f16(S_[ni], qa[kk][0].x, qa[kk][1].x, qa[kk][0].z, qa[kk][1].z, bb.x, bb.z);
                mma_f16(S_[ni], qa[kk][0].x, qa[kk][1].x, qa[kk][0].z, qa[kk][1].z, bb.y, bb.w);
                mma_f16(S_[ni], qa[kk][0].y, qa[kk][1].y, qa[kk][0].w, qa[kk][1].w, bb.x, bb.z);
            }
        }
        __syncthreads();                 // everyone done reading K(t)
        if (kt + 1 < 16) LOADV(kt+1, bK);   // V(t+1) -> K(t)'s buffer
        asm volatile("cp.async.commit_group;");

        // ---- scale + mask ----
        uint2 mg  = *(const uint2*)&mbg [kt*2];
        uint2 mg8 = *(const uint2*)&mbg8[kt*2];
        #pragma unroll
        for (int ni = 0; ni < 8; ni++){
            int c = ni*8 + 2*q;
            unsigned wg_  = (c < 32) ? mg.x  : mg.y;
            unsigned wg8_ = (c < 32) ? mg8.x : mg8.y;
            int bitp = c & 31;
            S_[ni][0] = ((wg_ >> bitp) & 1)      ? S_[ni][0]*0.125f : -1e9f;
            S_[ni][1] = ((wg_ >> (bitp+1)) & 1)  ? S_[ni][1]*0.125f : -1e9f;
            S_[ni][2] = ((wg8_ >> bitp) & 1)     ? S_[ni][2]*0.125f : -1e9f;
            S_[ni][3] = ((wg8_ >> (bitp+1)) & 1) ? S_[ni][3]*0.125f : -1e9f;
        }

        // ---- online softmax ----
        float rm0 = -3.0e38f, rm1 = -3.0e38f;
        #pragma unroll
        for (int ni = 0; ni < 8; ni++){
            rm0 = fmaxf(rm0, fmaxf(S_[ni][0], S_[ni][1]));
            rm1 = fmaxf(rm1, fmaxf(S_[ni][2], S_[ni][3]));
        }
        rm0 = fmaxf(rm0, __shfl_xor_sync(0xffffffffu, rm0, 1));
        rm0 = fmaxf(rm0, __shfl_xor_sync(0xffffffffu, rm0, 2));
        rm1 = fmaxf(rm1, __shfl_xor_sync(0xffffffffu, rm1, 1));
        rm1 = fmaxf(rm1, __shfl_xor_sync(0xffffffffu, rm1, 2));
        float m0n = fmaxf(m0, rm0), m1n = fmaxf(m1, rm1);
        float r0 = fexp(m0 - m0n), r1 = fexp(m1 - m1n);
        float ls0 = 0.f, ls1 = 0.f;
        #pragma unroll
        for (int ni = 0; ni < 8; ni++){
            S_[ni][0] = fexp(S_[ni][0] - m0n);
            S_[ni][1] = fexp(S_[ni][1] - m0n);
            S_[ni][2] = fexp(S_[ni][2] - m1n);
            S_[ni][3] = fexp(S_[ni][3] - m1n);
            ls0 += S_[ni][0] + S_[ni][1];
            ls1 += S_[ni][2] + S_[ni][3];
            Oa[ni][0] *= r0; Oa[ni][1] *= r0;
            Oa[ni][2] *= r1; Oa[ni][3] *= r1;
        }
        ls0 += __shfl_xor_sync(0xffffffffu, ls0, 1);
        ls0 += __shfl_xor_sync(0xffffffffu, ls0, 2);
        ls1 += __shfl_xor_sync(0xffffffffu, ls1, 1);
        ls1 += __shfl_xor_sync(0xffffffffu, ls1, 2);
        l0 = l0*r0 + ls0;
        l1 = l1*r1 + ls1;
        m0 = m0n; m1 = m1n;

        // ---- O += P @ V (fp16x3) ----
        #pragma unroll
        for (int kk = 0; kk < 4; kk++){
            unsigned h0,l0w,h1,l1w,h2,l2w,h3,l3w;
            split2(S_[2*kk  ][0], S_[2*kk  ][1], h0, l0w);
            split2(S_[2*kk  ][2], S_[2*kk  ][3], h1, l1w);
            split2(S_[2*kk+1][0], S_[2*kk+1][1], h2, l2w);
            split2(S_[2*kk+1][2], S_[2*kk+1][3], h3, l3w);
            #pragma unroll
            for (int ni = 0; ni < 8; ni++){
                uint4 bb = *(const uint4*)&skv[bV*4096 + (ni*8+g)*64 + kk*16 + 4*q];
                mma_f16(Oa[ni], h0, h1, h2, h3, bb.x, bb.z);
                mma_f16(Oa[ni], h0, h1, h2, h3, bb.y, bb.w);
                mma_f16(Oa[ni], l0w, l1w, l2w, l3w, bb.x, bb.z);
            }
        }
        __syncthreads();                 // everyone done reading V(t)
        if (kt + 2 < 16) LOADK(kt+2, bV);   // K(t+2) -> V(t)'s buffer
        asm volatile("cp.async.commit_group;");
    }
    #undef LOADK
    #undef LOADV

    // ---- finalize ----
    float i0 = 1.f / l0, i1 = 1.f / l1;
    long long rg  = (tokB + qrow_g ) * DM;
    long long rg8 = (tokB + qrow_g8) * DM;
    #pragma unroll
    for (int ni = 0; ni < 8; ni++){
        int c = ni*8 + 2*q;
        int w = hlw(h*32 + (c >> 1));
        unsigned hh, ll;
        split2(Oa[ni][0]*i0, Oa[ni][1]*i0, hh, ll);
        *(uint2*)&O[rg + w]  = make_uint2(hh, ll);
        split2(Oa[ni][2]*i1, Oa[ni][3]*i1, hh, ll);
        *(uint2*)&O[rg8 + w] = make_uint2(hh, ll);
    }
}

// ---------------- fp16x3 GEMM on HL operands ----------------
template<int NTILES>
__global__ __launch_bounds__(256,2) void gemm_hh_kernel(
    const unsigned* __restrict__ A, const unsigned* __restrict__ B,
    float* __restrict__ Cf, unsigned* __restrict__ Ch,
    int M, int N, int K, int ldaw, int ldbw, int ldc,
    int innerN,
    long long sAo, long long sAi, long long sBo, long long sBi,
    long long sCo, long long sCi,
    const int* __restrict__ rowIdx, const int* __restrict__ tileExpert,
    long long expSB, float alpha, int actMode, int cT,
    MD md, int nMulti,
    const int* __restrict__ moeOff, const int* __restrict__ moeCnt)
{
    __shared__ unsigned As[3][128][16];
    __shared__ unsigned Bs[3][NTILES*16][16];

    int z  = blockIdx.z;
    int zo = z / innerN, zi = z - zo*innerN;
    if (nMulti > 0){
        A = md.a[zi];
        Cf = md.f[zi]; Ch = md.h[zi];
        ldc = md.ldc[zi]; cT = md.cT[zi];
    }
    const int tm0 = blockIdx.y * 128;
    const int tn0 = blockIdx.x * (NTILES*16);
    if (moeCnt){
        int e = tileExpert[blockIdx.y];
        if (tm0 >= moeOff[e] + moeCnt[e]) return;
    }
    A += zo*sAo + zi*sAi;
    long long boff = zo*sBo + zi*sBi;
    if (tileExpert) boff += (long long)tileExpert[blockIdx.y] * expSB;
    B += boff;
    long long coff = zo*sCo + zi*sCi;

    const int tid = threadIdx.x;
    const int lane = tid & 31;
    const int warp = tid >> 5;
    const int wm = (warp & 3) * 32;
    const int wn = (warp >> 2) * (NTILES*8);
    const int g = lane >> 2;
    const int q = lane & 3;

    const int lrow = tid >> 1;
    const int lsel = tid & 1;
    int grow = tm0 + lrow;
    bool aval = grow < M;
    int srcRow = aval ? (rowIdx ? (rowIdx[grow] & (NTOK-1)) : grow) : 0;
    const unsigned* Ap = A + (long long)srcRow * ldaw + lsel*8;
    unsigned aS = (unsigned)__cvta_generic_to_shared(&As[0][0][0])
                  + (unsigned)((lrow*16 + lsel*8)*4);

    const int tprB = 256/(NTILES*16);
    const int bwords = 16/tprB;
    const int browL = tid / tprB;
    const int bseg = tid % tprB;
    bool bval = (tn0 + browL) < N;
    int brow = bval ? (tn0 + browL) : 0;
    const unsigned* Bp = B + (long long)brow * ldbw + bseg*bwords;
    unsigned bS = (unsigned)__cvta_generic_to_shared(&Bs[0][0][0])
                  + (unsigned)((browL*16 + bseg*bwords)*4);
    const unsigned bStage = (unsigned)(NTILES*16*16*4);

    float acc[2][NTILES][4];
    #pragma unroll
    for (int mi=0;mi<2;mi++)
        #pragma unroll
        for (int ni=0;ni<NTILES;ni++)
            #pragma unroll
            for (int t=0;t<4;t++) acc[mi][ni][t]=0.f;

    const int nt = K >> 4;

    #define ISSUE_AT(T, ST) do{                                   \
        int _t = (T);                                              \
        if (_t < nt){                                              \
            unsigned _boA = (unsigned)((ST) * 8192);               \
            unsigned _boB = (unsigned)(ST) * bStage;               \
            int _kn = _t * 16;                                     \
            cp16(aS + _boA,      Ap + _kn,     aval);              \
            cp16(aS + _boA + 16, Ap + _kn + 4, aval);              \
            cp16(bS + _boB,      Bp + _kn,     bval);              \
            if (bwords == 8)                                       \
                cp16(bS + _boB + 16, Bp + _kn + 4, bval);          \
        }                                                          \
        asm volatile("cp.async.commit_group;");                    \
    }while(0)

    ISSUE_AT(0, 0);
    ISSUE_AT(1, 1);

    int buf = 0, fill = 2;
    for (int k = 0; k < nt; k++){
        asm volatile("cp.async.wait_group 1;");
        __syncthreads();
        ISSUE_AT(k+2, fill);
        {
            uint4 a1[2], a2[2];
            #pragma unroll
            for (int mi = 0; mi < 2; mi++){
                int row = wm + mi*16 + g;
                a1[mi] = *(const uint4*)&As[buf][row  ][4*q];
                a2[mi] = *(const uint4*)&As[buf][row+8][4*q];
            }
            #pragma unroll
            for (int ni = 0; ni < NTILES; ni++){
                int col = wn + ni*8 + g;
                uint4 bb = *(const uint4*)&Bs[buf][col][4*q];
                #pragma unroll
                for (int mi = 0; mi < 2; mi++){
                    mma_f16(acc[mi][ni], a1[mi].x, a2[mi].x, a1[mi].z, a2[mi].z, bb.x, bb.z);
                    mma_f16(acc[mi][ni], a1[mi].x, a2[mi].x, a1[mi].z, a2[mi].z, bb.y, bb.w);
                    mma_f16(acc[mi][ni], a1[mi].y, a2[mi].y, a1[mi].w, a2[mi].w, bb.x, bb.z);
                }
            }
        }
        buf  = (buf  == 2) ? 0 : buf  + 1;
        fill = (fill == 2) ? 0 : fill + 1;
    }
    #undef ISSUE_AT

    float* CfP = Cf ? (Cf + coff) : (float*)0;
    unsigned* ChP = Ch ? (Ch + coff) : (unsigned*)0;
    #pragma unroll
    for (int mi = 0; mi < 2; mi++){
        #pragma unroll
        for (int rr = 0; rr < 2; rr++){
            int row = tm0 + wm + mi*16 + g + rr*8;
            if (row >= M) continue;
            #pragma unroll
            for (int ni = 0; ni < NTILES; ni++){
                int col = tn0 + wn + ni*8 + q*2;
                if (col >= N) continue;
                float v0 = acc[mi][ni][rr*2+0] * alpha;
                float v1 = acc[mi][ni][rr*2+1] * alpha;
                if (actMode == 1){
                    v0 = 0.5f * v0 * (1.f + erff(v0 * 0.70710678118654752f));
                    v1 = 0.5f * v1 * (1.f + erff(v1 * 0.70710678118654752f));
                }
                if (!cT){
                    if (CfP) *(float2*)&CfP[(long long)row*ldc + col] = make_float2(v0, v1);
                    if (ChP){
                        unsigned h,l; split2(v0,v1,h,l);
                        *(uint2*)&ChP[(long long)row*ldc + hlw(col>>1)] = make_uint2(h,l);
                    }
                } else {
                    int W = hlw(row >> 1);
                    int hs = row & 1;
                    {
                        __half h0 = __float2half_rn(v0);
                        unsigned* p = ChP + (long long)col*ldc;
                        ((__half*)(p + W    ))[hs] = h0;
                        ((__half*)(p + W + 1))[hs] = __float2half_rn(v0 - __half2float(h0));
                    }
                    if (col + 1 < N){
                        __half h1 = __float2half_rn(v1);
                        unsigned* p = ChP + (long long)(col+1)*ldc;
                        ((__half*)(p + W    ))[hs] = h1;
                        ((__half*)(p + W + 1))[hs] = __float2half_rn(v1 - __half2float(h1));
                    }
                }
            }
        }
    }
}

// ---------------- delta branch ----------------
__global__ __launch_bounds__(256) void ctx1_kernel(const float* __restrict__ kd,
                                                   const float* __restrict__ vd,
                                                   float* __restrict__ ctxp,
                                                   float* __restrict__ ksump){
    int z = blockIdx.x >> 2;
    int chunk = blockIdx.x & 3;
    int b = z >> 4, h = z & 15;
    const float* kbase = kd + ((long long)b*SEQ)*DM + h*DK;
    const float* vbase = vd + ((long long)b*SEQ)*DM + h*DK;
    __shared__ float ks[64][65];
    __shared__ float vs[64][65];
    int tid = threadIdx.x;
    int d0 = (tid >> 4) << 2;
    int e0 = (tid & 15) << 2;
    float acc[4][4];
    #pragma unroll
    for (int i=0;i<4;i++)
        #pragma unroll
        for (int j=0;j<4;j++) acc[i][j]=0.f;
    float ksacc = 0.f;

    for (int s0 = chunk*256; s0 < chunk*256+256; s0 += 64) {
        for (int t = tid; t < 64*16; t += 256) {
            int rr = t >> 4; int cc = (t & 15) << 2;
            float4 kv = *(const float4*)(kbase + (long long)(s0+rr)*DM + cc);
            float4 vv = *(const float4*)(vbase + (long long)(s0+rr)*DM + cc);
            ks[rr][cc+0]=kv.x; ks[rr][cc+1]=kv.y; ks[rr][cc+2]=kv.z; ks[rr][cc+3]=kv.w;
            vs[rr][cc+0]=vv.x; vs[rr][cc+1]=vv.y; vs[rr][cc+2]=vv.z; vs[rr][cc+3]=vv.w;
        }
        __syncthreads();
        if (tid < DK){
            #pragma unroll 8
            for (int rr=0; rr<64; rr++) ksacc += fmaxf(ks[rr][tid], 0.f);
        }
        #pragma unroll 4
        for (int ss=0; ss<64; ss++){
            float kr[4], vr[4];
            #pragma unroll
            for (int i=0;i<4;i++) kr[i]=ks[ss][d0+i];
            #pragma unroll
            for (int j=0;j<4;j++) vr[j]=vs[ss][e0+j];
            #pragma unroll
            for (int i=0;i<4;i++)
                #pragma unroll
                for (int j=0;j<4;j++) acc[i][j] += kr[i]*vr[j];
        }
        __syncthreads();
    }
    float* cbase = ctxp + ((long long)z*4 + chunk)*DK*DK;
    #pragma unroll
    for (int i=0;i<4;i++)
        #pragma unroll
        for (int j=0;j<4;j++)
            cbase[(d0+i)*DK + e0+j] = acc[i][j];
    if (tid < DK) ksump[((long long)z*4 + chunk)*DK + tid] = ksacc;
}

__global__ void ctx2_kernel(const float* __restrict__ ctxp, float* __restrict__ ctx,
                            const float* __restrict__ ksump, float* __restrict__ ksum){
    int z = blockIdx.x;
    const float* p = ctxp + (long long)z*4*DK*DK;
    float* o = ctx + (long long)z*DK*DK;
    for (int i = threadIdx.x; i < DK*DK; i += 256)
        o[i] = p[i] + p[DK*DK + i] + p[2*DK*DK + i] + p[3*DK*DK + i];
    if (threadIdx.x < DK){
        int d = threadIdx.x;
        float s = 0.f;
        #pragma unroll
        for (int c=0;c<4;c++) s += ksump[((long long)z*4 + c)*DK + d];
        ksum[z*DK + d] = s;
    }
}

__global__ __launch_bounds__(256) void delta_kernel(const float* __restrict__ qd,
                                                    const float* __restrict__ ctx,
                                                    const float* __restrict__ ksum,
                                                    unsigned* __restrict__ du){
    int z = blockIdx.x >> 2;
    int sc = blockIdx.x & 3;
    int b = z >> 4, h = z & 15;
    __shared__ float cs[DK*DK];
    __shared__ float kss[DK];
    for (int i = threadIdx.x; i < DK*DK; i += 256) cs[i] = ctx[(long long)z*DK*DK + i];
    if (threadIdx.x < DK) kss[threadIdx.x] = ksum[z*DK + threadIdx.x];
    __syncthreads();
    int s = sc*256 + threadIdx.x;
    const float* qrow = qd + ((long long)(b*SEQ + s))*DM + h*DK;
    float q[DK];
    #pragma unroll
    for (int d=0; d<DK; d+=4){
        float4 v = *(const float4*)(qrow + d);
        q[d+0]=fmaxf(v.x,0.f); q[d+1]=fmaxf(v.y,0.f);
        q[d+2]=fmaxf(v.z,0.f); q[d+3]=fmaxf(v.w,0.f);
    }
    float zv = 1e-6f;
    #pragma unroll
    for (int d=0; d<DK; d++) zv += q[d]*kss[d];
    float invz = 1.f / zv;
    unsigned* ob = du + ((long long)(b*SEQ + s))*DM + h*DK;
    for (int e=0; e<DK; e+=2){
        float a0 = 0.f, a1 = 0.f;
        #pragma unroll
        for (int d=0; d<DK; d++){
            a0 += q[d]*cs[d*DK + e];
            a1 += q[d]*cs[d*DK + e+1];
        }
        unsigned hh,ll; split2(a0*invz, a1*invz, hh, ll);
        *(uint2*)&ob[hlw(e>>1)] = make_uint2(hh,ll);
    }
}

// ---------------- router / moe plumbing / final ----------------
__global__ __launch_bounds__(256) void router_kernel(const float* __restrict__ xn2,
                                                     const float* __restrict__ wr,
                                                     int* __restrict__ topk_idx,
                                                     float* __restrict__ topk_w,
                                                     int* __restrict__ counts){
    int t = blockIdx.x;
    float p[NE];
    #pragma unroll
    for (int e=0;e<NE;e++) p[e]=0.f;
    for (int k = threadIdx.x; k < DM; k += 256){
        float xv = xn2[(long long)t*DM + k];
        #pragma unroll
        for (int e=0;e<NE;e++) p[e] += xv*wr[k*NE + e];
    }
    __shared__ float part[NE][8];
    int w = threadIdx.x >> 5;
    #pragma unroll
    for (int e=0;e<NE;e++){
        float v = warpSum(p[e]);
        if ((threadIdx.x & 31)==0) part[e][w] = v;
    }
    __syncthreads();
    if (threadIdx.x == 0){
        float lg[NE];
        for (int e=0;e<NE;e++){
            float s=0.f;
            for (int ww=0; ww<8; ww++) s += part[e][ww];
            lg[e]=s;
        }
        int i0=0; float v0=lg[0];
        for (int e=1;e<NE;e++) if (lg[e]>v0){v0=lg[e];i0=e;}
        int i1=-1; float v1=-3.0e38f;
        for (int e=0;e<NE;e++) if (e!=i0 && lg[e]>v1){v1=lg[e];i1=e;}
        float e1 = expf(v1-v0);
        float inv = 1.f/(1.f+e1);
        topk_idx[t*2+0]=i0; topk_idx[t*2+1]=i1;
        topk_w[t*2+0]=inv;  topk_w[t*2+1]=e1*inv;
        atomicAdd(&counts[i0],1); atomicAdd(&counts[i1],1);
    }
}

__global__ void prep_kernel(int* counts, int* cursor, int* tok){
    int i = blockIdx.x*256 + threadIdx.x;
    if (i < NE){ counts[i]=0; cursor[i]=0; }
    if (i < PAIR_CAP) tok[i]=0;
}

__global__ void scan_kernel(const int* counts, int* off, int* tile_e){
    if (threadIdx.x==0 && blockIdx.x==0){
        int o = 0;
        off[0]=0;
        for (int e=0;e<NE;e++){ o += (counts[e]+127)&~127; off[e+1]=o; }
        for (int t=0;t<NTILE72;t++){
            int row = t*128;
            int ee = NE-1;
            for (int i=0;i<NE;i++){ if (row < off[i+1]) { ee=i; break; } }
            tile_e[t]=ee;
        }
    }
}

__global__ void place_kernel(const int* __restrict__ topk_idx,
                             const int* __restrict__ off,
                             int* cursor, int* tok, int* pair_pos){
    int t = blockIdx.x*256 + threadIdx.x;
    if (t >= NTOK) return;
    for (int k=0;k<2;k++){
        int e = topk_idx[t*2+k];
        int pos = atomicAdd(&cursor[e],1);
        int r = off[e] + pos;
        tok[r] = t;
        pair_pos[t*2+k] = r;
    }
}

__global__ void final_kernel(const float* __restrict__ x1,
                             const float* __restrict__ y2,
                             const float* __restrict__ topk_w,
                             const int* __restrict__ pair_pos,
                             float* __restrict__ out){
    long long i = ((long long)blockIdx.x*256 + threadIdx.x) * 4;
    int t = (int)(i >> 10);
    int c = (int)(i & 1023);
    float w0 = topk_w[t*2+0], w1 = topk_w[t*2+1];
    long long b0 = (long long)pair_pos[t*2+0]*DM + c;
    long long b1 = (long long)pair_pos[t*2+1]*DM + c;
    float4 a  = *(const float4*)&x1[i];
    float4 y0 = *(const float4*)&y2[b0];
    float4 y1 = *(const float4*)&y2[b1];
    float4 r;
    r.x = a.x + w0*y0.x + w1*y1.x;
    r.y = a.y + w0*y0.y + w1*y1.y;
    r.z = a.z + w0*y0.z + w1*y1.z;
    r.w = a.w + w0*y0.w + w1*y1.w;
    *(float4*)&out[i] = r;
}

// ---------------- host side ----------------
static void gemm(const unsigned* A, const unsigned* B,
                 float* Cf, unsigned* Ch,
                 int M, int N, int K, int ldaw, int ldbw, int ldc,
                 int batch, int innerN,
                 long long sAo, long long sAi, long long sBo, long long sBi,
                 long long sCo, long long sCi,
                 const int* rowIdx, const int* tileE, long long expSB,
                 float alpha, int act, int cT,
                 const MD& md, int nMulti,
                 const int* moeOff, const int* moeCnt){
    dim3 grid((N+127)/128, (M+127)/128, batch);
    gemm_hh_kernel<8><<<grid, 256>>>(A,B,Cf,Ch,M,N,K,ldaw,ldbw,ldc,innerN,
                                     sAo,sAi,sBo,sBi,sCo,sCi,
                                     rowIdx,tileE,expSB,alpha,act,cT,md,nMulti,
                                     moeOff,moeCnt);
}

extern "C" void kernel_launch(void* const* d_in, const int* in_sizes, int n_in,
                              void* d_out, int out_size){
    const float* x        = (const float*)d_in[0];
    const int*   mask     = (const int*)  d_in[1];
    const float* ln1_g    = (const float*)d_in[2];
    const float* ln1_b    = (const float*)d_in[3];
    const float* wq       = (const float*)d_in[4];
    const float* wk       = (const float*)d_in[5];
    const float* wv       = (const float*)d_in[6];
    const float* wo       = (const float*)d_in[7];
    const float* wqd      = (const float*)d_in[8];
    const float* wkd      = (const float*)d_in[9];
    const float* wvd      = (const float*)d_in[10];
    const float* wod      = (const float*)d_in[11];
    const float* w_gate   = (const float*)d_in[12];
    const float* ln2_g    = (const float*)d_in[13];
    const float* ln2_b    = (const float*)d_in[14];
    const float* w_router = (const float*)d_in[15];
    const float* e_w1     = (const float*)d_in[16];
    const float* e_w2     = (const float*)d_in[17];
    float* out = (float*)d_out;

    float *xn1,*qd,*kd,*vd,*dense_o,*delta_o,*x1,*xn2,*ctx,*ctxp,*ksum,*ksump,*y2,*topk_w;
    int *topk_idx,*counts,*cursor,*off,*tile_e,*tok,*pair_pos;
    unsigned *xn1u,*qu,*ku,*vTu,*actu,*dlu,*xn2u,*h1u,*wu,*e1u,*e2u,*mb;

    cudaGetSymbolAddress((void**)&xn1,     g_xn1);
    cudaGetSymbolAddress((void**)&qd,      g_qd);
    cudaGetSymbolAddress((void**)&kd,      g_kd);
    cudaGetSymbolAddress((void**)&vd,      g_vd);
    cudaGetSymbolAddress((void**)&dense_o, g_dense_o);
    cudaGetSymbolAddress((void**)&delta_o, g_delta_o);
    cudaGetSymbolAddress((void**)&x1,      g_x1);
    cudaGetSymbolAddress((void**)&xn2,     g_xn2);
    cudaGetSymbolAddress((void**)&ctx,     g_ctx);
    cudaGetSymbolAddress((void**)&ctxp,    g_ctxp);
    cudaGetSymbolAddress((void**)&ksum,    g_ksum);
    cudaGetSymbolAddress((void**)&ksump,   g_ksump);
    cudaGetSymbolAddress((void**)&y2,      g_y2);
    cudaGetSymbolAddress((void**)&topk_w,  g_topk_w);
    cudaGetSymbolAddress((void**)&topk_idx,g_topk_idx);
    cudaGetSymbolAddress((void**)&counts,  g_counts);
    cudaGetSymbolAddress((void**)&cursor,  g_cursor);
    cudaGetSymbolAddress((void**)&off,     g_off);
    cudaGetSymbolAddress((void**)&tile_e,  g_tile_e);
    cudaGetSymbolAddress((void**)&tok,     g_tok);
    cudaGetSymbolAddress((void**)&pair_pos,g_pair_pos);
    cudaGetSymbolAddress((void**)&xn1u,    g_xn1u);
    cudaGetSymbolAddress((void**)&qu,      g_qu);
    cudaGetSymbolAddress((void**)&ku,      g_ku);
    cudaGetSymbolAddress((void**)&vTu,     g_vTu);
    cudaGetSymbolAddress((void**)&actu,    g_actu);
    cudaGetSymbolAddress((void**)&dlu,     g_dlu);
    cudaGetSymbolAddress((void**)&xn2u,    g_xn2u);
    cudaGetSymbolAddress((void**)&h1u,     g_h1u);
    cudaGetSymbolAddress((void**)&wu,      g_wu);
    cudaGetSymbolAddress((void**)&e1u,     g_e1u);
    cudaGetSymbolAddress((void**)&e2u,     g_e2u);
    cudaGetSymbolAddress((void**)&mb,      g_mb);

    MD md0; memset(&md0, 0, sizeof(md0));

    // 0: LN1 (+ fused mask bit-pack)
    ln_kernel<<<NTOK,256>>>(x, ln1_g, ln1_b, xn1, xn1u, mask, mb);
    // 1: dense weight splits
    WP8 wp;
    wp.p[0]=wq; wp.p[1]=wk; wp.p[2]=wv; wp.p[3]=wqd;
    wp.p[4]=wkd; wp.p[5]=wvd; wp.p[6]=wo; wp.p[7]=wod;
    wsplit8_kernel<<<dim3(32,32,8), dim3(32,8)>>>(wp, wu);

    // 2: all 6 projections (batched)
    {
        MD md; memset(&md, 0, sizeof(md));
        for (int z=0; z<6; z++){ md.a[z]=xn1u; md.ldc[z]=DM; md.cT[z]=0; }
        md.h[0]=qu;
        md.h[1]=ku;
        md.h[2]=vTu; md.ldc[2]=NTOK; md.cT[2]=1;
        md.f[3]=qd;
        md.f[4]=kd;
        md.f[5]=vd;
        gemm(xn1u, wu, 0,0,
             NTOK,DM,DM, DM,DM,DM, 6,6,
             0,0, 0,WSZ, 0,0,
             0,0,0, 1.f,0,0, md, 6, 0,0);
    }

    // 3: fused flash attention (pipelined KV) -> actu   <-- ncu target
    fattn_kernel<<<dim3(SEQ/128, NB*NH), 256>>>(qu, ku, vTu, mb, actu);

    // delta branch (ksum fused)
    ctx1_kernel<<<NB*NH*4, 256>>>(kd, vd, ctxp, ksump);
    ctx2_kernel<<<NB*NH, 256>>>(ctxp, ctx, ksump, ksum);
    delta_kernel<<<NB*NH*4, 256>>>(qd, ctx, ksum, dlu);

    // output projections, batched 2
    {
        MD md; memset(&md, 0, sizeof(md));
        md.a[0]=actu; md.f[0]=dense_o; md.ldc[0]=DM; md.cT[0]=0;
        md.a[1]=dlu;  md.f[1]=delta_o; md.ldc[1]=DM; md.cT[1]=0;
        gemm(actu, wu+6LL*WSZ, 0,0,
             NTOK,DM,DM, DM,DM,DM, 2,2,
             0,0, 0,WSZ, 0,0,
             0,0,0, 1.f,0,0, md, 2, 0,0);
    }

    // fused gate + combine + LN2
    combine_ln_kernel<<<NTOK,256>>>(x, dense_o, delta_o, xn1, w_gate,
                                    ln2_g, ln2_b, x1, xn2, xn2u);

    // routing
    prep_kernel<<<(PAIR_CAP+255)/256, 256>>>(counts, cursor, tok);
    router_kernel<<<NTOK, 256>>>(xn2, w_router, topk_idx, topk_w, counts);
    scan_kernel<<<1,32>>>(counts, off, tile_e);
    place_kernel<<<(NTOK+255)/256, 256>>>(topk_idx, off, cursor, tok, pair_pos);

    // expert weight splits
    wsplit_kernel<<<dim3(DFF/32, DM/32, NE), dim3(32,8)>>>(e_w1, e1u, DM, DFF);

    // expert GEMM1 (gathered, gelu) -> h1 HL ; pad tiles skipped
    gemm(xn2u, e1u, 0,h1u, PAIR_CAP,DFF,DM, DM,DM,DFF,
         1,1, 0,0,0,0,0,0,
         tok, tile_e, (long long)DM*DFF, 1.f,1,0, md0, 0, off, counts);

    wsplit_kernel<<<dim3(DM/32, DFF/32, NE), dim3(32,8)>>>(e_w2, e2u, DFF, DM);

    // expert GEMM2 -> y2 fp32 ; pad tiles skipped
    gemm(h1u, e2u, y2,0, PAIR_CAP,DM,DFF, DFF,DFF,DM,
         1,1, 0,0,0,0,0,0,
         0, tile_e, (long long)DFF*DM, 1.f,0,0, md0, 0, off, counts);

    // final combine (float4)
    final_kernel<<<NTOK*DM/1024, 256>>>(x1, y2, topk_w, pair_pos, out);
}

// round 17
// speedup vs baseline: 1.2540x; 1.1134x over previous
#include <cuda_runtime.h>
#include <cuda_fp16.h>
#include <math.h>

#define NTOK 4096
#define DM   1024
#define DFF  2048
#define NH   16
#define DK   64
#define NB   4
#define SEQ  1024
#define NE   8
#define PAIR_CAP 9216
#define NTILE72  72
#define WSZ  (1024*1024)

// ---------------- fp32 scratch ----------------
__device__ float g_qd [NTOK*DM];
__device__ float g_kd [NTOK*DM];
__device__ float g_vd [NTOK*DM];
__device__ float g_dense_o[NTOK*DM];
__device__ float g_delta_o[NTOK*DM];
__device__ float g_x1 [NTOK*DM];
__device__ float g_xn1[NTOK*DM];
__device__ float g_xn2[NTOK*DM];
__device__ float g_ctx [NB*NH*DK*DK];
__device__ float g_ctxp[NB*NH*4*DK*DK];
__device__ float g_ksum[NB*NH*DK];
__device__ float g_ksump[NB*NH*4*DK];
__device__ float g_y2[(long long)PAIR_CAP*DM];
__device__ int   g_topk_idx[NTOK*2];
__device__ float g_topk_w [NTOK*2];
__device__ int   g_counts[NE];
__device__ int   g_cursor[NE];
__device__ int   g_off[NE+1];
__device__ int   g_tile_e[NTILE72];
__device__ int   g_tok[PAIR_CAP];
__device__ int   g_pair_pos[NTOK*2];
__device__ unsigned g_mb[NB*SEQ*32];     // packed mask bits

// ---------------- HL scratch ----------------
__device__ unsigned g_xn1u[NTOK*DM];
__device__ unsigned g_qu  [NTOK*DM];
__device__ unsigned g_ku  [NTOK*DM];
__device__ unsigned g_vTu [DM*NTOK];
__device__ unsigned g_actu[NTOK*DM];
__device__ unsigned g_dlu [NTOK*DM];
__device__ unsigned g_xn2u[NTOK*DM];
__device__ unsigned g_h1u [(long long)PAIR_CAP*DFF];
__device__ unsigned g_wu  [8LL*WSZ];
__device__ unsigned g_e1u [8LL*DM*DFF];
__device__ unsigned g_e2u [8LL*DFF*DM];

struct MD {
    const unsigned* a[6];
    float* f[6]; unsigned* h[6];
    int ldc[6]; int cT[6];
};

// ---------------- perm helpers ----------------
__device__ __forceinline__ int pperm(int p){ return ((p&3)<<1) | (p>>2); }
__device__ __forceinline__ int hlw(int p){ return 2*(p & ~7) + 2*pperm(p & 7); }

// ---------------- low-level ----------------
__device__ __forceinline__ void mma_f16(float* d,
        unsigned a0, unsigned a1, unsigned a2, unsigned a3,
        unsigned b0, unsigned b1){
    asm volatile("mma.sync.aligned.m16n8k16.row.col.f32.f16.f16.f32 "
        "{%0,%1,%2,%3}, {%4,%5,%6,%7}, {%8,%9}, {%0,%1,%2,%3};"
        : "+f"(d[0]),"+f"(d[1]),"+f"(d[2]),"+f"(d[3])
        : "r"(a0),"r"(a1),"r"(a2),"r"(a3),"r"(b0),"r"(b1));
}
__device__ __forceinline__ unsigned packh(__half x, __half y){
    return (unsigned)__half_as_ushort(x) | ((unsigned)__half_as_ushort(y) << 16);
}
__device__ __forceinline__ void split2(float x, float y, unsigned& hi, unsigned& lo){
    __half hx = __float2half_rn(x), hy = __float2half_rn(y);
    __half lx = __float2half_rn(x - __half2float(hx));
    __half ly = __float2half_rn(y - __half2float(hy));
    hi = packh(hx, hy);
    lo = packh(lx, ly);
}
__device__ __forceinline__ void cp16(unsigned saddr, const void* g, bool v){
    asm volatile("cp.async.ca.shared.global [%0], [%1], 16, %2;"
        :: "r"(saddr), "l"(g), "r"(v ? 16 : 0));
}
__device__ __forceinline__ float fexp(float v){
    float y = v * 1.4426950408889634f;
    y = fmaxf(y, -126.0f);
    float n = floorf(y);
    float f = y - n;
    float p = 1.5403530e-4f;
    p = fmaf(p, f, 1.3333558e-3f);
    p = fmaf(p, f, 9.6181291e-3f);
    p = fmaf(p, f, 5.5504109e-2f);
    p = fmaf(p, f, 2.4022651e-1f);
    p = fmaf(p, f, 6.9314718e-1f);
    p = fmaf(p, f, 1.0f);
    return __int_as_float(((int)n + 127) << 23) * p;
}

__device__ __forceinline__ float warpSum(float v){
    #pragma unroll
    for (int o=16;o;o>>=1) v += __shfl_xor_sync(0xffffffffu, v, o);
    return v;
}
__device__ __forceinline__ float blockSum(float v, float* red){
    v = warpSum(v);
    if ((threadIdx.x & 31) == 0) red[threadIdx.x>>5] = v;
    __syncthreads();
    if (threadIdx.x < 32) {
        float t = (threadIdx.x < 8) ? red[threadIdx.x] : 0.f;
        t = warpSum(t);
        if (threadIdx.x == 0) red[0] = t;
    }
    __syncthreads();
    float r = red[0];
    __syncthreads();
    return r;
}

// ---------------- weight transpose + split -> HL ----------------
struct WP8 { const float* p[8]; };

__global__ void wsplit8_kernel(WP8 wp, unsigned* __restrict__ oB){
    __shared__ float ts[32][33];
    int mat = blockIdx.z;
    const float* W = wp.p[mat];
    unsigned* o = oB + (long long)mat*WSZ;
    int k0 = blockIdx.y*32, n0 = blockIdx.x*32;
    int tx = threadIdx.x, ty = threadIdx.y;
    #pragma unroll
    for (int i=0;i<4;i++)
        ts[ty+8*i][tx] = W[(long long)(k0+ty+8*i)*DM + n0 + tx];
    __syncthreads();
    int tid = ty*32 + tx;
    #pragma unroll
    for (int it=0; it<2; it++){
        int item = it*256 + tid;
        int n = item >> 4;
        int pr = item & 15;
        unsigned h,l; split2(ts[2*pr][n], ts[2*pr+1][n], h, l);
        *(uint2*)&o[(long long)(n0+n)*DM + hlw((k0>>1)+pr)] = make_uint2(h,l);
    }
}

__global__ void wsplit_kernel(const float* __restrict__ W,
                              unsigned* __restrict__ o, int K, int N){
    __shared__ float ts[32][33];
    W += (long long)blockIdx.z * K * N;
    o += (long long)blockIdx.z * K * N;
    int k0 = blockIdx.y*32, n0 = blockIdx.x*32;
    int tx = threadIdx.x, ty = threadIdx.y;
    #pragma unroll
    for (int i=0;i<4;i++)
        ts[ty+8*i][tx] = W[(long long)(k0+ty+8*i)*N + n0 + tx];
    __syncthreads();
    int tid = ty*32 + tx;
    #pragma unroll
    for (int it=0; it<2; it++){
        int item = it*256 + tid;
        int n = item >> 4;
        int pr = item & 15;
        unsigned h,l; split2(ts[2*pr][n], ts[2*pr+1][n], h, l);
        *(uint2*)&o[(long long)(n0+n)*K + hlw((k0>>1)+pr)] = make_uint2(h,l);
    }
}

// ---------------- layernorm (fp32 + HL out, optional mask bit-pack) ----------------
__global__ __launch_bounds__(256) void ln_kernel(const float* __restrict__ x,
                                                 const float* __restrict__ g,
                                                 const float* __restrict__ b,
                                                 float* __restrict__ y,
                                                 unsigned* __restrict__ yu,
                                                 const int* __restrict__ mask,
                                                 unsigned* __restrict__ mb){
    __shared__ float row[DM];
    __shared__ float red[8];
    long long base = (long long)blockIdx.x * DM;
    if (mask){
        int warp = threadIdx.x >> 5, lane = threadIdx.x & 31;
        const int* mrow = mask + base;
        #pragma unroll
        for (int w0 = warp; w0 < 32; w0 += 8){
            unsigned bits = __ballot_sync(0xffffffffu, mrow[w0*32 + lane] != 0);
            if (lane == 0) mb[blockIdx.x*32 + w0] = bits;
        }
    }
    float s = 0.f;
    for (int i = threadIdx.x; i < DM; i += 256) { float v = x[base+i]; row[i] = v; s += v; }
    s = blockSum(s, red);
    float mu = s * (1.f/DM);
    float vs = 0.f;
    for (int i = threadIdx.x; i < DM; i += 256) { float d = row[i]-mu; vs += d*d; }
    vs = blockSum(vs, red);
    float rstd = rsqrtf(vs * (1.f/DM) + 1e-5f);
    unsigned* ob = yu + base;
    for (int i2 = threadIdx.x; i2 < DM/2; i2 += 256){
        int i = i2*2;
        float v0 = (row[i  ]-mu)*rstd*g[i  ] + b[i  ];
        float v1 = (row[i+1]-mu)*rstd*g[i+1] + b[i+1];
        if (y){ y[base+i] = v0; y[base+i+1] = v1; }
        unsigned h,l; split2(v0,v1,h,l);
        *(uint2*)&ob[hlw(i2)] = make_uint2(h,l);
    }
}

// ---------------- fused gate + combine + LN2 ----------------
__global__ __launch_bounds__(256) void combine_ln_kernel(
    const float* __restrict__ x, const float* __restrict__ dense,
    const float* __restrict__ delta, const float* __restrict__ xn1,
    const float* __restrict__ wg,
    const float* __restrict__ g, const float* __restrict__ b,
    float* __restrict__ x1, float* __restrict__ y, unsigned* __restrict__ yu)
{
    __shared__ float row[DM];
    __shared__ float red[8];
    long long base = (long long)blockIdx.x * DM;
    float p0=0.f, p1=0.f;
    for (int i = threadIdx.x; i < DM; i += 256){
        float xv = xn1[base+i];
        p0 += xv*wg[i*2+0];
        p1 += xv*wg[i*2+1];
    }
    p0 = blockSum(p0, red);
    p1 = blockSum(p1, red);
    float m = fmaxf(p0,p1);
    float e0 = expf(p0-m), e1 = expf(p1-m);
    float inv = 1.f/(e0+e1);
    float g0 = e0*inv, g1 = e1*inv;
    float s = 0.f;
    for (int i = threadIdx.x; i < DM; i += 256){
        float v = x[base+i] + g0*dense[base+i] + g1*delta[base+i];
        row[i] = v; x1[base+i] = v; s += v;
    }
    s = blockSum(s, red);
    float mu = s * (1.f/DM);
    float vs = 0.f;
    for (int i = threadIdx.x; i < DM; i += 256){ float d2 = row[i]-mu; vs += d2*d2; }
    vs = blockSum(vs, red);
    float rstd = rsqrtf(vs * (1.f/DM) + 1e-5f);
    unsigned* ob = yu + base;
    for (int i2 = threadIdx.x; i2 < DM/2; i2 += 256){
        int i = i2*2;
        float v0 = (row[i  ]-mu)*rstd*g[i  ] + b[i  ];
        float v1 = (row[i+1]-mu)*rstd*g[i+1] + b[i+1];
        y[base+i] = v0; y[base+i+1] = v1;
        unsigned h,l; split2(v0,v1,h,l);
        *(uint2*)&ob[hlw(i2)] = make_uint2(h,l);
    }
}

// ---------------- fused flash attention (3-buffer KV pipeline, fp16x2) ----------------
__global__ __launch_bounds__(256,2) void fattn_kernel(
    const unsigned* __restrict__ Q, const unsigned* __restrict__ Kt,
    const unsigned* __restrict__ Vt, const unsigned* __restrict__ mb,
    unsigned* __restrict__ O)
{
    __shared__ unsigned skv[12288];
    const int bh = blockIdx.y;
    const int b = bh >> 4, h = bh & 15;
    const int tm0 = blockIdx.x * 128;
    const int tid = threadIdx.x;
    const int lane = tid & 31;
    const int warp = tid >> 5;
    const int g = lane >> 2;
    const int q = lane & 3;
    const long long tokB = (long long)b * SEQ;

    unsigned sb = (unsigned)__cvta_generic_to_shared(&skv[0]);

    #pragma unroll
    for (int j = 0; j < 8; j++){
        int w = tid*4 + j*1024;
        int row = w >> 6, col = w & 63;
        cp16(sb + w*4, Q + (tokB + tm0 + row)*DM + h*64 + col, true);
    }
    asm volatile("cp.async.commit_group;");
    asm volatile("cp.async.wait_group 0;");
    __syncthreads();
    uint4 qa[4][2];
    {
        int r0 = warp*16 + g;
        #pragma unroll
        for (int kk = 0; kk < 4; kk++){
            qa[kk][0] = *(const uint4*)&skv[r0*64      + kk*16 + 4*q];
            qa[kk][1] = *(const uint4*)&skv[(r0+8)*64  + kk*16 + 4*q];
        }
    }
    __syncthreads();

    #define LOADK(T, BUF) do{                                                        \
        _Pragma("unroll")                                                            \
        for (int j = 0; j < 4; j++){                                                 \
            int w = tid*4 + j*1024;                                                  \
            int row = w >> 6, col = w & 63;                                          \
            cp16(sb + ((BUF)*4096 + w)*4,                                            \
                 Kt + (tokB + (T)*64 + row)*DM + h*64 + col, true);                  \
        }                                                                            \
    }while(0)
    #define LOADV(T, BUF) do{                                                        \
        _Pragma("unroll")                                                            \
        for (int j = 0; j < 4; j++){                                                 \
            int w = tid*4 + j*1024;                                                  \
            int row = w >> 6, col = w & 63;                                          \
            cp16(sb + ((BUF)*4096 + w)*4,                                            \
                 Vt + (long long)(h*64 + row)*NTOK + tokB + (T)*64 + col, true);     \
        }                                                                            \
    }while(0)

    LOADK(0, 0); LOADV(0, 1);
    asm volatile("cp.async.commit_group;");
    LOADK(1, 2);
    asm volatile("cp.async.commit_group;");

    float m0 = -3.0e38f, m1 = -3.0e38f, l0 = 0.f, l1 = 0.f;
    float Oa[8][4];
    #pragma unroll
    for (int ni=0;ni<8;ni++)
        #pragma unroll
        for (int t=0;t<4;t++) Oa[ni][t] = 0.f;

    const int qrow_g  = tm0 + warp*16 + g;
    const int qrow_g8 = qrow_g + 8;
    const unsigned* mbg  = mb + ((long long)(b*SEQ + qrow_g ))*32;
    const unsigned* mbg8 = mb + ((long long)(b*SEQ + qrow_g8))*32;

    for (int kt = 0; kt < 16; kt++){
        const int bK = (2*kt) % 3;
        const int bV = (2*kt+1) % 3;
        asm volatile("cp.async.wait_group 1;");
        __syncthreads();

        // ---- S = Q @ K^T (fp16x2: Q-hi x K-full) ----
        float S_[8][4];
        #pragma unroll
        for (int ni=0;ni<8;ni++)
            #pragma unroll
            for (int t=0;t<4;t++) S_[ni][t] = 0.f;
        #pragma unroll
        for (int kk = 0; kk < 4; kk++){
            #pragma unroll
            for (int ni = 0; ni < 8; ni++){
                uint4 bb = *(const uint4*)&skv[bK*4096 + (ni*8+g)*64 + kk*16 + 4*q];
                mma_f16(S_[ni], qa[kk][0].x, qa[kk][1].x, qa[kk][0].z, qa[kk][1].z, bb.x, bb.z);
                mma_f16(S_[ni], qa[kk][0].x, qa[kk][1].x, qa[kk][0].z, qa[kk][1].z, bb.y, bb.w);
            }
        }
        __syncthreads();
        if (kt + 1 < 16) LOADV(kt+1, bK);
        asm volatile("cp.async.commit_group;");

        // ---- scale + mask ----
        uint2 mg  = *(const uint2*)&mbg [kt*2];
        uint2 mg8 = *(const uint2*)&mbg8[kt*2];
        #pragma unroll
        for (int ni = 0; ni < 8; ni++){
            int c = ni*8 + 2*q;
            unsigned wg_  = (c < 32) ? mg.x  : mg.y;
            unsigned wg8_ = (c < 32) ? mg8.x : mg8.y;
            int bitp = c & 31;
            S_[ni][0] = ((wg_ >> bitp) & 1)      ? S_[ni][0]*0.125f : -1e9f;
            S_[ni][1] = ((wg_ >> (bitp+1)) & 1)  ? S_[ni][1]*0.125f : -1e9f;
            S_[ni][2] = ((wg8_ >> bitp) & 1)     ? S_[ni][2]*0.125f : -1e9f;
            S_[ni][3] = ((wg8_ >> (bitp+1)) & 1) ? S_[ni][3]*0.125f : -1e9f;
        }

        // ---- online softmax ----
        float rm0 = -3.0e38f, rm1 = -3.0e38f;
        #pragma unroll
        for (int ni = 0; ni < 8; ni++){
            rm0 = fmaxf(rm0, fmaxf(S_[ni][0], S_[ni][1]));
            rm1 = fmaxf(rm1, fmaxf(S_[ni][2], S_[ni][3]));
        }
        rm0 = fmaxf(rm0, __shfl_xor_sync(0xffffffffu, rm0, 1));
        rm0 = fmaxf(rm0, __shfl_xor_sync(0xffffffffu, rm0, 2));
        rm1 = fmaxf(rm1, __shfl_xor_sync(0xffffffffu, rm1, 1));
        rm1 = fmaxf(rm1, __shfl_xor_sync(0xffffffffu, rm1, 2));
        float m0n = fmaxf(m0, rm0), m1n = fmaxf(m1, rm1);
        float r0 = fexp(m0 - m0n), r1 = fexp(m1 - m1n);
        float ls0 = 0.f, ls1 = 0.f;
        #pragma unroll
        for (int ni = 0; ni < 8; ni++){
            S_[ni][0] = fexp(S_[ni][0] - m0n);
            S_[ni][1] = fexp(S_[ni][1] - m0n);
            S_[ni][2] = fexp(S_[ni][2] - m1n);
            S_[ni][3] = fexp(S_[ni][3] - m1n);
            ls0 += S_[ni][0] + S_[ni][1];
            ls1 += S_[ni][2] + S_[ni][3];
            Oa[ni][0] *= r0; Oa[ni][1] *= r0;
            Oa[ni][2] *= r1; Oa[ni][3] *= r1;
        }
        ls0 += __shfl_xor_sync(0xffffffffu, ls0, 1);
        ls0 += __shfl_xor_sync(0xffffffffu, ls0, 2);
        ls1 += __shfl_xor_sync(0xffffffffu, ls1, 1);
        ls1 += __shfl_xor_sync(0xffffffffu, ls1, 2);
        l0 = l0*r0 + ls0;
        l1 = l1*r1 + ls1;
        m0 = m0n; m1 = m1n;

        // ---- O += P @ V (fp16x2: P-hi x V-full) ----
        #pragma unroll
        for (int kk = 0; kk < 4; kk++){
            unsigned h0 = packh(__float2half_rn(S_[2*kk  ][0]), __float2half_rn(S_[2*kk  ][1]));
            unsigned h1 = packh(__float2half_rn(S_[2*kk  ][2]), __float2half_rn(S_[2*kk  ][3]));
            unsigned h2 = packh(__float2half_rn(S_[2*kk+1][0]), __float2half_rn(S_[2*kk+1][1]));
            unsigned h3 = packh(__float2half_rn(S_[2*kk+1][2]), __float2half_rn(S_[2*kk+1][3]));
            #pragma unroll
            for (int ni = 0; ni < 8; ni++){
                uint4 bb = *(const uint4*)&skv[bV*4096 + (ni*8+g)*64 + kk*16 + 4*q];
                mma_f16(Oa[ni], h0, h1, h2, h3, bb.x, bb.z);
                mma_f16(Oa[ni], h0, h1, h2, h3, bb.y, bb.w);
            }
        }
        __syncthreads();
        if (kt + 2 < 16) LOADK(kt+2, bV);
        asm volatile("cp.async.commit_group;");
    }
    #undef LOADK
    #undef LOADV

    float i0 = 1.f / l0, i1 = 1.f / l1;
    long long rg  = (tokB + qrow_g ) * DM;
    long long rg8 = (tokB + qrow_g8) * DM;
    #pragma unroll
    for (int ni = 0; ni < 8; ni++){
        int c = ni*8 + 2*q;
        int w = hlw(h*32 + (c >> 1));
        unsigned hh, ll;
        split2(Oa[ni][0]*i0, Oa[ni][1]*i0, hh, ll);
        *(uint2*)&O[rg + w]  = make_uint2(hh, ll);
        split2(Oa[ni][2]*i1, Oa[ni][3]*i1, hh, ll);
        *(uint2*)&O[rg8 + w] = make_uint2(hh, ll);
    }
}

// ---------------- fp16x2 GEMM on HL operands (A-hi x B-full) ----------------
template<int NTILES>
__global__ __launch_bounds__(256,2) void gemm_hh_kernel(
    const unsigned* __restrict__ A, const unsigned* __restrict__ B,
    float* __restrict__ Cf, unsigned* __restrict__ Ch,
    int M, int N, int K, int ldaw, int ldbw, int ldc,
    int innerN,
    long long sAo, long long sAi, long long sBo, long long sBi,
    long long sCo, long long sCi,
    const int* __restrict__ rowIdx, const int* __restrict__ tileExpert,
    long long expSB, float alpha, int actMode, int cT,
    MD md, int nMulti,
    const int* __restrict__ moeOff, const int* __restrict__ moeCnt)
{
    __shared__ unsigned As[3][128][16];
    __shared__ unsigned Bs[3][NTILES*16][16];

    int z  = blockIdx.z;
    int zo = z / innerN, zi = z - zo*innerN;
    if (nMulti > 0){
        A = md.a[zi];
        Cf = md.f[zi]; Ch = md.h[zi];
        ldc = md.ldc[zi]; cT = md.cT[zi];
    }
    const int tm0 = blockIdx.y * 128;
    const int tn0 = blockIdx.x * (NTILES*16);
    if (moeCnt){
        int e = tileExpert[blockIdx.y];
        if (tm0 >= moeOff[e] + moeCnt[e]) return;
    }
    A += zo*sAo + zi*sAi;
    long long boff = zo*sBo + zi*sBi;
    if (tileExpert) boff += (long long)tileExpert[blockIdx.y] * expSB;
    B += boff;
    long long coff = zo*sCo + zi*sCi;

    const int tid = threadIdx.x;
    const int lane = tid & 31;
    const int warp = tid >> 5;
    const int wm = (warp & 3) * 32;
    const int wn = (warp >> 2) * (NTILES*8);
    const int g = lane >> 2;
    const int q = lane & 3;

    const int lrow = tid >> 1;
    const int lsel = tid & 1;
    int grow = tm0 + lrow;
    bool aval = grow < M;
    int srcRow = aval ? (rowIdx ? (rowIdx[grow] & (NTOK-1)) : grow) : 0;
    const unsigned* Ap = A + (long long)srcRow * ldaw + lsel*8;
    unsigned aS = (unsigned)__cvta_generic_to_shared(&As[0][0][0])
                  + (unsigned)((lrow*16 + lsel*8)*4);

    const int tprB = 256/(NTILES*16);
    const int bwords = 16/tprB;
    const int browL = tid / tprB;
    const int bseg = tid % tprB;
    bool bval = (tn0 + browL) < N;
    int brow = bval ? (tn0 + browL) : 0;
    const unsigned* Bp = B + (long long)brow * ldbw + bseg*bwords;
    unsigned bS = (unsigned)__cvta_generic_to_shared(&Bs[0][0][0])
                  + (unsigned)((browL*16 + bseg*bwords)*4);
    const unsigned bStage = (unsigned)(NTILES*16*16*4);

    float acc[2][NTILES][4];
    #pragma unroll
    for (int mi=0;mi<2;mi++)
        #pragma unroll
        for (int ni=0;ni<NTILES;ni++)
            #pragma unroll
            for (int t=0;t<4;t++) acc[mi][ni][t]=0.f;

    const int nt = K >> 4;

    #define ISSUE_AT(T, ST) do{                                   \
        int _t = (T);                                              \
        if (_t < nt){                                              \
            unsigned _boA = (unsigned)((ST) * 8192);               \
            unsigned _boB = (unsigned)(ST) * bStage;               \
            int _kn = _t * 16;                                     \
            cp16(aS + _boA,      Ap + _kn,     aval);              \
            cp16(aS + _boA + 16, Ap + _kn + 4, aval);              \
            cp16(bS + _boB,      Bp + _kn,     bval);              \
            if (bwords == 8)                                       \
                cp16(bS + _boB + 16, Bp + _kn + 4, bval);          \
        }                                                          \
        asm volatile("cp.async.commit_group;");                    \
    }while(0)

    ISSUE_AT(0, 0);
    ISSUE_AT(1, 1);

    int buf = 0, fill = 2;
    for (int k = 0; k < nt; k++){
        asm volatile("cp.async.wait_group 1;");
        __syncthreads();
        ISSUE_AT(k+2, fill);
        {
            uint4 a1[2], a2[2];
            #pragma unroll
            for (int mi = 0; mi < 2; mi++){
                int row = wm + mi*16 + g;
                a1[mi] = *(const uint4*)&As[buf][row  ][4*q];
                a2[mi] = *(const uint4*)&As[buf][row+8][4*q];
            }
            #pragma unroll
            for (int ni = 0; ni < NTILES; ni++){
                int col = wn + ni*8 + g;
                uint4 bb = *(const uint4*)&Bs[buf][col][4*q];
                #pragma unroll
                for (int mi = 0; mi < 2; mi++){
                    mma_f16(acc[mi][ni], a1[mi].x, a2[mi].x, a1[mi].z, a2[mi].z, bb.x, bb.z);
                    mma_f16(acc[mi][ni], a1[mi].x, a2[mi].x, a1[mi].z, a2[mi].z, bb.y, bb.w);
                }
            }
        }
        buf  = (buf  == 2) ? 0 : buf  + 1;
        fill = (fill == 2) ? 0 : fill + 1;
    }
    #undef ISSUE_AT

    float* CfP = Cf ? (Cf + coff) : (float*)0;
    unsigned* ChP = Ch ? (Ch + coff) : (unsigned*)0;
    #pragma unroll
    for (int mi = 0; mi < 2; mi++){
        #pragma unroll
        for (int rr = 0; rr < 2; rr++){
            int row = tm0 + wm + mi*16 + g + rr*8;
            if (row >= M) continue;
            #pragma unroll
            for (int ni = 0; ni < NTILES; ni++){
                int col = tn0 + wn + ni*8 + q*2;
                if (col >= N) continue;
                float v0 = acc[mi][ni][rr*2+0] * alpha;
                float v1 = acc[mi][ni][rr*2+1] * alpha;
                if (actMode == 1){
                    v0 = 0.5f * v0 * (1.f + erff(v0 * 0.70710678118654752f));
                    v1 = 0.5f * v1 * (1.f + erff(v1 * 0.70710678118654752f));
                }
                if (!cT){
                    if (CfP) *(float2*)&CfP[(long long)row*ldc + col] = make_float2(v0, v1);
                    if (ChP){
                        unsigned h,l; split2(v0,v1,h,l);
                        *(uint2*)&ChP[(long long)row*ldc + hlw(col>>1)] = make_uint2(h,l);
                    }
                } else {
                    int W = hlw(row >> 1);
                    int hs = row & 1;
                    {
                        __half h0 = __float2half_rn(v0);
                        unsigned* p = ChP + (long long)col*ldc;
                        ((__half*)(p + W    ))[hs] = h0;
                        ((__half*)(p + W + 1))[hs] = __float2half_rn(v0 - __half2float(h0));
                    }
                    if (col + 1 < N){
                        __half h1 = __float2half_rn(v1);
                        unsigned* p = ChP + (long long)(col+1)*ldc;
                        ((__half*)(p + W    ))[hs] = h1;
                        ((__half*)(p + W + 1))[hs] = __float2half_rn(v1 - __half2float(h1));
                    }
                }
            }
        }
    }
}

// ---------------- delta branch ----------------
__global__ __launch_bounds__(256) void ctx1_kernel(const float* __restrict__ kd,
                                                   const float* __restrict__ vd,
                                                   float* __restrict__ ctxp,
                                                   float* __restrict__ ksump){
    int z = blockIdx.x >> 2;
    int chunk = blockIdx.x & 3;
    int b = z >> 4, h = z & 15;
    const float* kbase = kd + ((long long)b*SEQ)*DM + h*DK;
    const float* vbase = vd + ((long long)b*SEQ)*DM + h*DK;
    __shared__ float ks[64][65];
    __shared__ float vs[64][65];
    int tid = threadIdx.x;
    int d0 = (tid >> 4) << 2;
    int e0 = (tid & 15) << 2;
    float acc[4][4];
    #pragma unroll
    for (int i=0;i<4;i++)
        #pragma unroll
        for (int j=0;j<4;j++) acc[i][j]=0.f;
    float ksacc = 0.f;

    for (int s0 = chunk*256; s0 < chunk*256+256; s0 += 64) {
        for (int t = tid; t < 64*16; t += 256) {
            int rr = t >> 4; int cc = (t & 15) << 2;
            float4 kv = *(const float4*)(kbase + (long long)(s0+rr)*DM + cc);
            float4 vv = *(const float4*)(vbase + (long long)(s0+rr)*DM + cc);
            ks[rr][cc+0]=kv.x; ks[rr][cc+1]=kv.y; ks[rr][cc+2]=kv.z; ks[rr][cc+3]=kv.w;
            vs[rr][cc+0]=vv.x; vs[rr][cc+1]=vv.y; vs[rr][cc+2]=vv.z; vs[rr][cc+3]=vv.w;
        }
        __syncthreads();
        if (tid < DK){
            #pragma unroll 8
            for (int rr=0; rr<64; rr++) ksacc += fmaxf(ks[rr][tid], 0.f);
        }
        #pragma unroll 4
        for (int ss=0; ss<64; ss++){
            float kr[4], vr[4];
            #pragma unroll
            for (int i=0;i<4;i++) kr[i]=ks[ss][d0+i];
            #pragma unroll
            for (int j=0;j<4;j++) vr[j]=vs[ss][e0+j];
            #pragma unroll
            for (int i=0;i<4;i++)
                #pragma unroll
                for (int j=0;j<4;j++) acc[i][j] += kr[i]*vr[j];
        }
        __syncthreads();
    }
    float* cbase = ctxp + ((long long)z*4 + chunk)*DK*DK;
    #pragma unroll
    for (int i=0;i<4;i++)
        #pragma unroll
        for (int j=0;j<4;j++)
            cbase[(d0+i)*DK + e0+j] = acc[i][j];
    if (tid < DK) ksump[((long long)z*4 + chunk)*DK + tid] = ksacc;
}

__global__ void ctx2_kernel(const float* __restrict__ ctxp, float* __restrict__ ctx,
                            const float* __restrict__ ksump, float* __restrict__ ksum){
    int z = blockIdx.x;
    const float* p = ctxp + (long long)z*4*DK*DK;
    float* o = ctx + (long long)z*DK*DK;
    for (int i = threadIdx.x; i < DK*DK; i += 256)
        o[i] = p[i] + p[DK*DK + i] + p[2*DK*DK + i] + p[3*DK*DK + i];
    if (threadIdx.x < DK){
        int d = threadIdx.x;
        float s = 0.f;
        #pragma unroll
        for (int c=0;c<4;c++) s += ksump[((long long)z*4 + c)*DK + d];
        ksum[z*DK + d] = s;
    }
}

__global__ __launch_bounds__(256) void delta_kernel(const float* __restrict__ qd,
                                                    const float* __restrict__ ctx,
                                                    const float* __restrict__ ksum,
                                                    unsigned* __restrict__ du){
    int z = blockIdx.x >> 2;
    int sc = blockIdx.x & 3;
    int b = z >> 4, h = z & 15;
    __shared__ float cs[DK*DK];
    __shared__ float kss[DK];
    for (int i = threadIdx.x; i < DK*DK; i += 256) cs[i] = ctx[(long long)z*DK*DK + i];
    if (threadIdx.x < DK) kss[threadIdx.x] = ksum[z*DK + threadIdx.x];
    __syncthreads();
    int s = sc*256 + threadIdx.x;
    const float* qrow = qd + ((long long)(b*SEQ + s))*DM + h*DK;
    float q[DK];
    #pragma unroll
    for (int d=0; d<DK; d+=4){
        float4 v = *(const float4*)(qrow + d);
        q[d+0]=fmaxf(v.x,0.f); q[d+1]=fmaxf(v.y,0.f);
        q[d+2]=fmaxf(v.z,0.f); q[d+3]=fmaxf(v.w,0.f);
    }
    float zv = 1e-6f;
    #pragma unroll
    for (int d=0; d<DK; d++) zv += q[d]*kss[d];
    float invz = 1.f / zv;
    unsigned* ob = du + ((long long)(b*SEQ + s))*DM + h*DK;
    for (int e=0; e<DK; e+=2){
        float a0 = 0.f, a1 = 0.f;
        #pragma unroll
        for (int d=0; d<DK; d++){
            a0 += q[d]*cs[d*DK + e];
            a1 += q[d]*cs[d*DK + e+1];
        }
        unsigned hh,ll; split2(a0*invz, a1*invz, hh, ll);
        *(uint2*)&ob[hlw(e>>1)] = make_uint2(hh,ll);
    }
}

// ---------------- router / moe plumbing / final ----------------
__global__ __launch_bounds__(256) void router_kernel(const float* __restrict__ xn2,
                                                     const float* __restrict__ wr,
                                                     int* __restrict__ topk_idx,
                                                     float* __restrict__ topk_w,
                                                     int* __restrict__ counts){
    int t = blockIdx.x;
    float p[NE];
    #pragma unroll
    for (int e=0;e<NE;e++) p[e]=0.f;
    for (int k = threadIdx.x; k < DM; k += 256){
        float xv = xn2[(long long)t*DM + k];
        #pragma unroll
        for (int e=0;e<NE;e++) p[e] += xv*wr[k*NE + e];
    }
    __shared__ float part[NE][8];
    int w = threadIdx.x >> 5;
    #pragma unroll
    for (int e=0;e<NE;e++){
        float v = warpSum(p[e]);
        if ((threadIdx.x & 31)==0) part[e][w] = v;
    }
    __syncthreads();
    if (threadIdx.x == 0){
        float lg[NE];
        for (int e=0;e<NE;e++){
            float s=0.f;
            for (int ww=0; ww<8; ww++) s += part[e][ww];
            lg[e]=s;
        }
        int i0=0; float v0=lg[0];
        for (int e=1;e<NE;e++) if (lg[e]>v0){v0=lg[e];i0=e;}
        int i1=-1; float v1=-3.0e38f;
        for (int e=0;e<NE;e++) if (e!=i0 && lg[e]>v1){v1=lg[e];i1=e;}
        float e1 = expf(v1-v0);
        float inv = 1.f/(1.f+e1);
        topk_idx[t*2+0]=i0; topk_idx[t*2+1]=i1;
        topk_w[t*2+0]=inv;  topk_w[t*2+1]=e1*inv;
        atomicAdd(&counts[i0],1); atomicAdd(&counts[i1],1);
    }
}

__global__ void prep_kernel(int* counts, int* cursor, int* tok){
    int i = blockIdx.x*256 + threadIdx.x;
    if (i < NE){ counts[i]=0; cursor[i]=0; }
    if (i < PAIR_CAP) tok[i]=0;
}

__global__ void scan_kernel(const int* counts, int* off, int* tile_e){
    if (threadIdx.x==0 && blockIdx.x==0){
        int o = 0;
        off[0]=0;
        for (int e=0;e<NE;e++){ o += (counts[e]+127)&~127; off[e+1]=o; }
        for (int t=0;t<NTILE72;t++){
            int row = t*128;
            int ee = NE-1;
            for (int i=0;i<NE;i++){ if (row < off[i+1]) { ee=i; break; } }
            tile_e[t]=ee;
        }
    }
}

__global__ void place_kernel(const int* __restrict__ topk_idx,
                             const int* __restrict__ off,
                             int* cursor, int* tok, int* pair_pos){
    int t = blockIdx.x*256 + threadIdx.x;
    if (t >= NTOK) return;
    for (int k=0;k<2;k++){
        int e = topk_idx[t*2+k];
        int pos = atomicAdd(&cursor[e],1);
        int r = off[e] + pos;
        tok[r] = t;
        pair_pos[t*2+k] = r;
    }
}

__global__ void final_kernel(const float* __restrict__ x1,
                             const float* __restrict__ y2,
                             const float* __restrict__ topk_w,
                             const int* __restrict__ pair_pos,
                             float* __restrict__ out){
    long long i = ((long long)blockIdx.x*256 + threadIdx.x) * 4;
    int t = (int)(i >> 10);
    int c = (int)(i & 1023);
    float w0 = topk_w[t*2+0], w1 = topk_w[t*2+1];
    long long b0 = (long long)pair_pos[t*2+0]*DM + c;
    long long b1 = (long long)pair_pos[t*2+1]*DM + c;
    float4 a  = *(const float4*)&x1[i];
    float4 y0 = *(const float4*)&y2[b0];
    float4 y1 = *(const float4*)&y2[b1];
    float4 r;
    r.x = a.x + w0*y0.x + w1*y1.x;
    r.y = a.y + w0*y0.y + w1*y1.y;
    r.z = a.z + w0*y0.z + w1*y1.z;
    r.w = a.w + w0*y0.w + w1*y1.w;
    *(float4*)&out[i] = r;
}

// ---------------- host side ----------------
static void gemm(const unsigned* A, const unsigned* B,
                 float* Cf, unsigned* Ch,
                 int M, int N, int K, int ldaw, int ldbw, int ldc,
                 int batch, int innerN,
                 long long sAo, long long sAi, long long sBo, long long sBi,
                 long long sCo, long long sCi,
                 const int* rowIdx, const int* tileE, long long expSB,
                 float alpha, int act, int cT,
                 const MD& md, int nMulti,
                 const int* moeOff, const int* moeCnt){
    dim3 grid((N+127)/128, (M+127)/128, batch);
    gemm_hh_kernel<8><<<grid, 256>>>(A,B,Cf,Ch,M,N,K,ldaw,ldbw,ldc,innerN,
                                     sAo,sAi,sBo,sBi,sCo,sCi,
                                     rowIdx,tileE,expSB,alpha,act,cT,md,nMulti,
                                     moeOff,moeCnt);
}

extern "C" void kernel_launch(void* const* d_in, const int* in_sizes, int n_in,
                              void* d_out, int out_size){
    const float* x        = (const float*)d_in[0];
    const int*   mask     = (const int*)  d_in[1];
    const float* ln1_g    = (const float*)d_in[2];
    const float* ln1_b    = (const float*)d_in[3];
    const float* wq       = (const float*)d_in[4];
    const float* wk       = (const float*)d_in[5];
    const float* wv       = (const float*)d_in[6];
    const float* wo       = (const float*)d_in[7];
    const float* wqd      = (const float*)d_in[8];
    const float* wkd      = (const float*)d_in[9];
    const float* wvd      = (const float*)d_in[10];
    const float* wod      = (const float*)d_in[11];
    const float* w_gate   = (const float*)d_in[12];
    const float* ln2_g    = (const float*)d_in[13];
    const float* ln2_b    = (const float*)d_in[14];
    const float* w_router = (const float*)d_in[15];
    const float* e_w1     = (const float*)d_in[16];
    const float* e_w2     = (const float*)d_in[17];
    float* out = (float*)d_out;

    float *xn1,*qd,*kd,*vd,*dense_o,*delta_o,*x1,*xn2,*ctx,*ctxp,*ksum,*ksump,*y2,*topk_w;
    int *topk_idx,*counts,*cursor,*off,*tile_e,*tok,*pair_pos;
    unsigned *xn1u,*qu,*ku,*vTu,*actu,*dlu,*xn2u,*h1u,*wu,*e1u,*e2u,*mb;

    cudaGetSymbolAddress((void**)&xn1,     g_xn1);
    cudaGetSymbolAddress((void**)&qd,      g_qd);
    cudaGetSymbolAddress((void**)&kd,      g_kd);
    cudaGetSymbolAddress((void**)&vd,      g_vd);
    cudaGetSymbolAddress((void**)&dense_o, g_dense_o);
    cudaGetSymbolAddress((void**)&delta_o, g_delta_o);
    cudaGetSymbolAddress((void**)&x1,      g_x1);
    cudaGetSymbolAddress((void**)&xn2,     g_xn2);
    cudaGetSymbolAddress((void**)&ctx,     g_ctx);
    cudaGetSymbolAddress((void**)&ctxp,    g_ctxp);
    cudaGetSymbolAddress((void**)&ksum,    g_ksum);
    cudaGetSymbolAddress((void**)&ksump,   g_ksump);
    cudaGetSymbolAddress((void**)&y2,      g_y2);
    cudaGetSymbolAddress((void**)&topk_w,  g_topk_w);
    cudaGetSymbolAddress((void**)&topk_idx,g_topk_idx);
    cudaGetSymbolAddress((void**)&counts,  g_counts);
    cudaGetSymbolAddress((void**)&cursor,  g_cursor);
    cudaGetSymbolAddress((void**)&off,     g_off);
    cudaGetSymbolAddress((void**)&tile_e,  g_tile_e);
    cudaGetSymbolAddress((void**)&tok,     g_tok);
    cudaGetSymbolAddress((void**)&pair_pos,g_pair_pos);
    cudaGetSymbolAddress((void**)&xn1u,    g_xn1u);
    cudaGetSymbolAddress((void**)&qu,      g_qu);
    cudaGetSymbolAddress((void**)&ku,      g_ku);
    cudaGetSymbolAddress((void**)&vTu,     g_vTu);
    cudaGetSymbolAddress((void**)&actu,    g_actu);
    cudaGetSymbolAddress((void**)&dlu,     g_dlu);
    cudaGetSymbolAddress((void**)&xn2u,    g_xn2u);
    cudaGetSymbolAddress((void**)&h1u,     g_h1u);
    cudaGetSymbolAddress((void**)&wu,      g_wu);
    cudaGetSymbolAddress((void**)&e1u,     g_e1u);
    cudaGetSymbolAddress((void**)&e2u,     g_e2u);
    cudaGetSymbolAddress((void**)&mb,      g_mb);

    MD md0; memset(&md0, 0, sizeof(md0));

    // 0: LN1 (+ fused mask bit-pack)
    ln_kernel<<<NTOK,256>>>(x, ln1_g, ln1_b, xn1, xn1u, mask, mb);
    // 1: dense weight splits
    WP8 wp;
    wp.p[0]=wq; wp.p[1]=wk; wp.p[2]=wv; wp.p[3]=wqd;
    wp.p[4]=wkd; wp.p[5]=wvd; wp.p[6]=wo; wp.p[7]=wod;
    wsplit8_kernel<<<dim3(32,32,8), dim3(32,8)>>>(wp, wu);

    // 2: all 6 projections (batched)
    {
        MD md; memset(&md, 0, sizeof(md));
        for (int z=0; z<6; z++){ md.a[z]=xn1u; md.ldc[z]=DM; md.cT[z]=0; }
        md.h[0]=qu;
        md.h[1]=ku;
        md.h[2]=vTu; md.ldc[2]=NTOK; md.cT[2]=1;
        md.f[3]=qd;
        md.f[4]=kd;
        md.f[5]=vd;
        gemm(xn1u, wu, 0,0,
             NTOK,DM,DM, DM,DM,DM, 6,6,
             0,0, 0,WSZ, 0,0,
             0,0,0, 1.f,0,0, md, 6, 0,0);
    }

    // 3: fused flash attention -> actu   <-- ncu target
    fattn_kernel<<<dim3(SEQ/128, NB*NH), 256>>>(qu, ku, vTu, mb, actu);

    // delta branch
    ctx1_kernel<<<NB*NH*4, 256>>>(kd, vd, ctxp, ksump);
    ctx2_kernel<<<NB*NH, 256>>>(ctxp, ctx, ksump, ksum);
    delta_kernel<<<NB*NH*4, 256>>>(qd, ctx, ksum, dlu);

    // output projections, batched 2
    {
        MD md; memset(&md, 0, sizeof(md));
        md.a[0]=actu; md.f[0]=dense_o; md.ldc[0]=DM; md.cT[0]=0;
        md.a[1]=dlu;  md.f[1]=delta_o; md.ldc[1]=DM; md.cT[1]=0;
        gemm(actu, wu+6LL*WSZ, 0,0,
             NTOK,DM,DM, DM,DM,DM, 2,2,
             0,0, 0,WSZ, 0,0,
             0,0,0, 1.f,0,0, md, 2, 0,0);
    }

    // fused gate + combine + LN2
    combine_ln_kernel<<<NTOK,256>>>(x, dense_o, delta_o, xn1, w_gate,
                                    ln2_g, ln2_b, x1, xn2, xn2u);

    // routing
    prep_kernel<<<(PAIR_CAP+255)/256, 256>>>(counts, cursor, tok);
    router_kernel<<<NTOK, 256>>>(xn2, w_router, topk_idx, topk_w, counts);
    scan_kernel<<<1,32>>>(counts, off, tile_e);
    place_kernel<<<(NTOK+255)/256, 256>>>(topk_idx, off, cursor, tok, pair_pos);

    // expert weight splits
    wsplit_kernel<<<dim3(DFF/32, DM/32, NE), dim3(32,8)>>>(e_w1, e1u, DM, DFF);

    // expert GEMM1 (gathered, gelu) -> h1 HL ; pad tiles skipped
    gemm(xn2u, e1u, 0,h1u, PAIR_CAP,DFF,DM, DM,DM,DFF,
         1,1, 0,0,0,0,0,0,
         tok, tile_e, (long long)DM*DFF, 1.f,1,0, md0, 0, off, counts);

    wsplit_kernel<<<dim3(DM/32, DFF/32, NE), dim3(32,8)>>>(e_w2, e2u, DFF, DM);

    // expert GEMM2 -> y2 fp32 ; pad tiles skipped
    gemm(h1u, e2u, y2,0, PAIR_CAP,DM,DFF, DFF,DFF,DM,
         1,1, 0,0,0,0,0,0,
         0, tile_e, (long long)DFF*DM, 1.f,0,0, md0, 0, off, counts);

    // final combine (float4)
    final_kernel<<<NTOK*DM/1024, 256>>>(x1, y2, topk_w, pair_pos, out);
}